// round 12
// baseline (speedup 1.0000x reference)
#include <cuda_runtime.h>
#include <cuda_bf16.h>
#include <cstdint>
#include <cstddef>

#define A_    3
#define T_    64
#define B_    256
#define ENTO_ 2048
#define EM_   1024
#define IN_   4096
#define N_    3072
#define MROWS 16384

// ---------------- device scratch (static globals; no allocation) ----------------
__device__ __nv_bfloat16 g_EntoS [3][(size_t)MROWS * ENTO_];  // phase1: ento bf16 splits
__device__ __nv_bfloat16 g_WentoS[3][(size_t)N_ * ENTO_];     // phase1: W_ento splits [n][k]
__device__ __align__(16) int8_t g_WQ[3][(size_t)N_ * N_];     // Wrec int8 slices [n][k]
__device__ __align__(16) int8_t g_VQ[2][3][B_ * N_];          // V int8 slices, ping-pong [b][n]
__device__ float         g_V [2][B_ * N_];                    // V fp32, ping-pong [b][n]

// ---------------- helpers ----------------
__device__ __forceinline__ uint32_t smem_u32(const void* p) {
    uint32_t a;
    asm("{ .reg .u64 t; cvta.to.shared.u64 t, %1; cvt.u32.u64 %0, t; }" : "=r"(a) : "l"(p));
    return a;
}
__device__ __forceinline__ void split3(float f, __nv_bfloat16& h, __nv_bfloat16& m,
                                       __nv_bfloat16& l) {
    h = __float2bfloat16(f);
    float r = f - __bfloat162float(h);
    m = __float2bfloat16(r);
    r = r - __bfloat162float(m);
    l = __float2bfloat16(r);
}
__device__ __forceinline__ int clamp7(int q) { return max(-127, min(127, q)); }

// w in (-2^-5, 2^-5): slices at 2^-12, 2^-19, 2^-26. Clamp EVERY slice to
// [-127,127]; residual recomputed vs the clamped value so the next slice
// absorbs clamp overshoot (no int8 wrap; worst-case residual ~2^-26).
__device__ __forceinline__ void quant3_w(float w, int8_t& a, int8_t& b, int8_t& c) {
    int q0 = clamp7(__float2int_rn(w * 4096.f));
    float r = w - q0 * (1.f / 4096.f);
    int q1 = clamp7(__float2int_rn(r * 524288.f));
    r -= q1 * (1.f / 524288.f);
    int q2 = clamp7(__float2int_rn(r * 67108864.f));
    a = (int8_t)q0; b = (int8_t)q1; c = (int8_t)q2;
}
// v in [-1, 1]: slices at 2^-7, 2^-14, 2^-21. Saturated v=±1 (common after
// clip) clamps through all 3 slices -> error exactly 2^-21/... = 4.8e-7.
__device__ __forceinline__ void quant3_v(float v, int8_t& a, int8_t& b, int8_t& c) {
    int q0 = clamp7(__float2int_rn(v * 128.f));
    float r = v - q0 * (1.f / 128.f);
    int q1 = clamp7(__float2int_rn(r * 16384.f));
    r -= q1 * (1.f / 16384.f);
    int q2 = clamp7(__float2int_rn(r * 2097152.f));
    a = (int8_t)q0; b = (int8_t)q1; c = (int8_t)q2;
}

#define LDSM4(r0, r1, r2, r3, addr) \
    asm volatile("ldmatrix.sync.aligned.m8n8.x4.shared.b16 {%0,%1,%2,%3}, [%4];" \
                 : "=r"(r0), "=r"(r1), "=r"(r2), "=r"(r3) : "r"(addr))

#define MMA16816(d, a, b) \
    asm volatile("mma.sync.aligned.m16n8k16.row.col.f32.bf16.bf16.f32 " \
                 "{%0,%1,%2,%3}, {%4,%5,%6,%7}, {%8,%9}, {%0,%1,%2,%3};" \
                 : "+f"((d)[0]), "+f"((d)[1]), "+f"((d)[2]), "+f"((d)[3]) \
                 : "r"((a)[0]), "r"((a)[1]), "r"((a)[2]), "r"((a)[3]), \
                   "r"((b)[0]), "r"((b)[1]))

#define IMMA16832(d, a, b0r, b1r) \
    asm volatile("mma.sync.aligned.m16n8k32.row.col.s32.s8.s8.s32 " \
                 "{%0,%1,%2,%3}, {%4,%5,%6,%7}, {%8,%9}, {%0,%1,%2,%3};" \
                 : "+r"((d)[0]), "+r"((d)[1]), "+r"((d)[2]), "+r"((d)[3]) \
                 : "r"((a)[0]), "r"((a)[1]), "r"((a)[2]), "r"((a)[3]), \
                   "r"(b0r), "r"(b1r))

#define CPASYNC16(dst, src) \
    asm volatile("cp.async.cg.shared.global [%0], [%1], 16;" :: "r"(dst), "l"(src))

// ---------------- prep kernels ----------------
__global__ void split_ento(const float* __restrict__ ento) {
    int k = blockIdx.x * 256 + threadIdx.x;
    size_t idx = (size_t)blockIdx.y * ENTO_ + k;
    __nv_bfloat16 h, m, l; split3(ento[idx], h, m, l);
    g_EntoS[0][idx] = h; g_EntoS[1][idx] = m; g_EntoS[2][idx] = l;
}
__global__ void split_wento(const float* __restrict__ w_ih) {
    int k = blockIdx.x * 256 + threadIdx.x;
    int n = blockIdx.y;
    float f = w_ih[(size_t)n * IN_ + k];
    __nv_bfloat16 h, m, l; split3(f, h, m, l);
    size_t idx = (size_t)n * ENTO_ + k;
    g_WentoS[0][idx] = h; g_WentoS[1][idx] = m; g_WentoS[2][idx] = l;
}
__global__ void quant_wrec(const float* __restrict__ w_ih, const float* __restrict__ w_hh) {
    int k = blockIdx.x * 256 + threadIdx.x;
    int n = blockIdx.y;
    int j = k >> 10, m_ = k & 1023;
    int a = n >> 10;
    float f;
    if (j == a) f = w_hh[(size_t)n * EM_ + m_];
    else {
        int pos = j - (j > a ? 1 : 0);
        f = w_ih[(size_t)n * IN_ + ENTO_ + pos * EM_ + m_];
    }
    int8_t q0, q1, q2; quant3_w(f, q0, q1, q2);
    size_t idx = (size_t)n * N_ + k;
    g_WQ[0][idx] = q0; g_WQ[1][idx] = q1; g_WQ[2][idx] = q2;
}
__global__ void quant_v0(const float* __restrict__ v0) {
    int n = blockIdx.x * 256 + threadIdx.x;
    int b = blockIdx.y;
    int j = n >> 10, m_ = n & 1023;
    float f = v0[((size_t)j * B_ + b) * EM_ + m_];
    g_V[0][b * N_ + n] = f;
    int8_t q0, q1, q2; quant3_v(f, q0, q1, q2);
    g_VQ[0][0][b * N_ + n] = q0;
    g_VQ[0][1][b * N_ + n] = q1;
    g_VQ[0][2][b * N_ + n] = q2;
}

// ---------------- Phase 1: bf16x3 HMMA (proven R8 path) ----------------
#define ASPLIT   10240
#define BSPLIT    5120
#define OFFB     30720
#define BUFSZ    46080
#define SMEM_P1  92160

__global__ __launch_bounds__(256) void phase1_gemm(float* __restrict__ dout) {
    constexpr int S = ENTO_ / 32;
    extern __shared__ char smem[];
    const uint32_t sb = smem_u32(smem);
    const int tid = threadIdx.x, wid = tid >> 5, lane = tid & 31;
    const int warp_m = wid & 3, warp_n = wid >> 2;
    const int n0 = blockIdx.x * 64;
    const int m0 = blockIdx.y * 128;

    float accH[2][4][4], accL[2][4][4], accS[2][4][4];
#pragma unroll
    for (int i = 0; i < 2; ++i)
#pragma unroll
        for (int j = 0; j < 4; ++j)
#pragma unroll
            for (int q = 0; q < 4; ++q) {
                accH[i][j][q] = 0.f; accL[i][j][q] = 0.f; accS[i][j][q] = 0.f;
            }

    auto loadChunk = [&](int s, uint32_t buf) {
        const int kb = s * 32;
#pragma unroll
        for (int i = 0; i < 9; ++i) {
            int u = tid + i * 256;
            const __nv_bfloat16* gp;
            uint32_t sa;
            if (u < 1536) {
                int sp = u >> 9, rem = u & 511, row = rem >> 2, un = rem & 3;
                gp = g_EntoS[sp] + (size_t)(m0 + row) * ENTO_ + kb + un * 8;
                sa = buf + sp * ASPLIT + row * 80 + un * 16;
            } else {
                int v = u - 1536;
                int sp = v >> 8, rem = v & 255, row = rem >> 2, un = rem & 3;
                gp = g_WentoS[sp] + (size_t)(n0 + row) * ENTO_ + kb + un * 8;
                sa = buf + OFFB + sp * BSPLIT + row * 80 + un * 16;
            }
            CPASYNC16(sa, gp);
        }
        asm volatile("cp.async.commit_group;" ::: "memory");
    };

    const int r16 = lane & 15, ahi = (lane >> 4) * 16;
    uint32_t aoff[2];
#pragma unroll
    for (int mt = 0; mt < 2; ++mt)
        aoff[mt] = (uint32_t)(warp_m * 32 + mt * 16 + r16) * 80 + ahi;
    const int bg = lane >> 3, bri = lane & 7;
    uint32_t boff[2];
#pragma unroll
    for (int p = 0; p < 2; ++p)
        boff[p] = (uint32_t)(warp_n * 32 + p * 16 + ((bg >> 1) << 3) + bri) * 80 + (bg & 1) * 16;

    loadChunk(0, sb);

    for (int s = 0; s < S; ++s) {
        if (s + 1 < S) {
            loadChunk(s + 1, sb + (uint32_t)((s + 1) & 1) * BUFSZ);
            asm volatile("cp.async.wait_group 1;" ::: "memory");
        } else {
            asm volatile("cp.async.wait_group 0;" ::: "memory");
        }
        __syncthreads();

        const uint32_t buf = sb + (uint32_t)(s & 1) * BUFSZ;
#pragma unroll
        for (int kk = 0; kk < 2; ++kk) {
            uint32_t af[3][2][4], bf[3][4][2];
#pragma unroll
            for (int sp = 0; sp < 3; ++sp) {
                uint32_t ab = buf + sp * ASPLIT + kk * 32;
#pragma unroll
                for (int mt = 0; mt < 2; ++mt)
                    LDSM4(af[sp][mt][0], af[sp][mt][1], af[sp][mt][2], af[sp][mt][3],
                          ab + aoff[mt]);
                uint32_t bb = buf + OFFB + sp * BSPLIT + kk * 32;
#pragma unroll
                for (int p = 0; p < 2; ++p)
                    LDSM4(bf[sp][2 * p][0], bf[sp][2 * p][1],
                          bf[sp][2 * p + 1][0], bf[sp][2 * p + 1][1],
                          bb + boff[p]);
            }
#pragma unroll
            for (int mt = 0; mt < 2; ++mt)
#pragma unroll
                for (int nt = 0; nt < 4; ++nt) {
                    MMA16816(accH[mt][nt], af[0][mt], bf[0][nt]);
                    MMA16816(accL[mt][nt], af[0][mt], bf[1][nt]);
                    MMA16816(accL[mt][nt], af[1][mt], bf[0][nt]);
                    MMA16816(accL[mt][nt], af[1][mt], bf[1][nt]);
                    MMA16816(accL[mt][nt], af[0][mt], bf[2][nt]);
                    MMA16816(accL[mt][nt], af[2][mt], bf[0][nt]);
                }
        }
        __syncthreads();

        if ((s & 3) == 3) {
#pragma unroll
            for (int mt = 0; mt < 2; ++mt)
#pragma unroll
                for (int nt = 0; nt < 4; ++nt)
#pragma unroll
                    for (int q = 0; q < 4; ++q) {
                        accS[mt][nt][q] += accH[mt][nt][q];
                        accH[mt][nt][q] = 0.f;
                    }
        }
    }

    const int l4 = lane >> 2, l2 = (lane & 3) * 2;
#pragma unroll
    for (int mt = 0; mt < 2; ++mt)
#pragma unroll
        for (int rh = 0; rh < 2; ++rh) {
            const int row = m0 + warp_m * 32 + mt * 16 + rh * 8 + l4;
#pragma unroll
            for (int nt = 0; nt < 4; ++nt) {
                const int c = n0 + warp_n * 32 + nt * 8 + l2;
                const int a = c >> 10, e = c & 1023;
                double x0 = (double)accS[mt][nt][rh * 2 + 0] + (double)accL[mt][nt][rh * 2 + 0];
                double x1 = (double)accS[mt][nt][rh * 2 + 1] + (double)accL[mt][nt][rh * 2 + 1];
                const int tt = row >> 8, b = row & 255;
                size_t oidx = ((size_t)((tt * 3 + a) * 256 + b)) * 1024 + e;
                *(float2*)&dout[oidx] = make_float2((float)x0, (float)x1);
            }
        }
}

// ---------------- Phase 2: int8 IMMA step ----------------
// CTA 128x48, 8 warps as 4(m)x2(n): warp tile 32x24 (2 mt x 3 nt m16n8 tiles).
// K staged 64 s8 (64B rows padded to 80B). grid (64, 2) = 128 CTAs.
// 3 exact s32 accumulator banks by product scale: 2^-19, 2^-26, 2^-33.
#define AQSP     10240           /* 128*80 */
#define BQSP      3840           /* 48*80  */
#define OFFBQ    30720           /* 3*AQSP */
#define BUFQ     42240           /* OFFBQ + 3*BQSP */
#define SMEM_ST  84480

__global__ __launch_bounds__(256) void step_imma(int par, int t, float* __restrict__ dout) {
    constexpr int S = N_ / 64;   // 48 stages
    extern __shared__ char smem[];
    const uint32_t sb = smem_u32(smem);
    const int tid = threadIdx.x, wid = tid >> 5, lane = tid & 31;
    const int warp_m = wid & 3, warp_n = wid >> 2;
    const int n0 = blockIdx.x * 48;
    const int m0 = blockIdx.y * 128;

    const int8_t* __restrict__ Aq = g_VQ[par][0];
    const size_t AQstride = (size_t)B_ * N_;
    const int8_t* __restrict__ Wq = g_WQ[0];
    const size_t WQstride = (size_t)N_ * N_;

    int acc0[2][3][4], acc1[2][3][4], acc2[2][3][4];
#pragma unroll
    for (int i = 0; i < 2; ++i)
#pragma unroll
        for (int j = 0; j < 3; ++j)
#pragma unroll
            for (int q = 0; q < 4; ++q) { acc0[i][j][q] = 0; acc1[i][j][q] = 0; acc2[i][j][q] = 0; }

    auto loadChunk = [&](int s, uint32_t buf) {
        const int kb = s * 64;
        for (int u = tid; u < 2112; u += 256) {
            const int8_t* gp;
            uint32_t sa;
            if (u < 1536) {                    // A: sp(3) x row(128) x un(4)
                int sp = u >> 9, rem = u & 511, row = rem >> 2, un = rem & 3;
                gp = Aq + sp * AQstride + (size_t)(m0 + row) * N_ + kb + un * 16;
                sa = buf + sp * AQSP + row * 80 + un * 16;
            } else {                           // B: sp(3) x row(48) x un(4)
                int v = u - 1536;
                int sp = v / 192, rem = v - sp * 192, row = rem >> 2, un = rem & 3;
                gp = Wq + sp * WQstride + (size_t)(n0 + row) * N_ + kb + un * 16;
                sa = buf + OFFBQ + sp * BQSP + row * 80 + un * 16;
            }
            CPASYNC16(sa, gp);
        }
        asm volatile("cp.async.commit_group;" ::: "memory");
    };

    // ldmatrix offsets
    uint32_t aoff[2];
#pragma unroll
    for (int mt = 0; mt < 2; ++mt)
        aoff[mt] = (uint32_t)(warp_m * 32 + mt * 16 + (lane & 15)) * 80 + (lane >> 4) * 16;
    uint32_t boff[3];
#pragma unroll
    for (int nt = 0; nt < 3; ++nt)
        boff[nt] = (uint32_t)(warp_n * 24 + nt * 8 + (lane & 7)) * 80 + (lane >> 3) * 16;

    loadChunk(0, sb);

    for (int s = 0; s < S; ++s) {
        if (s + 1 < S) {
            loadChunk(s + 1, sb + (uint32_t)((s + 1) & 1) * BUFQ);
            asm volatile("cp.async.wait_group 1;" ::: "memory");
        } else {
            asm volatile("cp.async.wait_group 0;" ::: "memory");
        }
        __syncthreads();

        const uint32_t buf = sb + (uint32_t)(s & 1) * BUFQ;

        // B frags: whole k64 per (slice, nt): regs [0,1]=k0-31, [2,3]=k32-63
        uint32_t bfr[3][3][4];
#pragma unroll
        for (int sp = 0; sp < 3; ++sp)
#pragma unroll
            for (int nt = 0; nt < 3; ++nt)
                LDSM4(bfr[sp][nt][0], bfr[sp][nt][1], bfr[sp][nt][2], bfr[sp][nt][3],
                      buf + OFFBQ + sp * BQSP + boff[nt]);

#pragma unroll
        for (int h = 0; h < 2; ++h) {
            uint32_t af[3][2][4];
#pragma unroll
            for (int sp = 0; sp < 3; ++sp)
#pragma unroll
                for (int mt = 0; mt < 2; ++mt)
                    LDSM4(af[sp][mt][0], af[sp][mt][1], af[sp][mt][2], af[sp][mt][3],
                          buf + sp * AQSP + aoff[mt] + h * 32);
#pragma unroll
            for (int mt = 0; mt < 2; ++mt)
#pragma unroll
                for (int nt = 0; nt < 3; ++nt) {
                    IMMA16832(acc0[mt][nt], af[0][mt], bfr[0][nt][2 * h], bfr[0][nt][2 * h + 1]);
                    IMMA16832(acc1[mt][nt], af[0][mt], bfr[1][nt][2 * h], bfr[1][nt][2 * h + 1]);
                    IMMA16832(acc1[mt][nt], af[1][mt], bfr[0][nt][2 * h], bfr[0][nt][2 * h + 1]);
                    IMMA16832(acc2[mt][nt], af[1][mt], bfr[1][nt][2 * h], bfr[1][nt][2 * h + 1]);
                    IMMA16832(acc2[mt][nt], af[0][mt], bfr[2][nt][2 * h], bfr[2][nt][2 * h + 1]);
                    IMMA16832(acc2[mt][nt], af[2][mt], bfr[0][nt][2 * h], bfr[0][nt][2 * h + 1]);
                }
        }
        __syncthreads();
    }

    // ---- epilogue: combine exact ints in double, clip, requantize ----
    const int l4 = lane >> 2, l2 = (lane & 3) * 2;
#pragma unroll
    for (int mt = 0; mt < 2; ++mt)
#pragma unroll
        for (int rh = 0; rh < 2; ++rh) {
            const int b = m0 + warp_m * 32 + mt * 16 + rh * 8 + l4;   // batch row
#pragma unroll
            for (int nt = 0; nt < 3; ++nt) {
                const int c = n0 + warp_n * 24 + nt * 8 + l2;
                const int a = c >> 10, e = c & 1023;
                double x0 = (double)acc0[mt][nt][rh * 2 + 0] * 0x1p-19
                          + (double)acc1[mt][nt][rh * 2 + 0] * 0x1p-26
                          + (double)acc2[mt][nt][rh * 2 + 0] * 0x1p-33;
                double x1 = (double)acc0[mt][nt][rh * 2 + 1] * 0x1p-19
                          + (double)acc1[mt][nt][rh * 2 + 1] * 0x1p-26
                          + (double)acc2[mt][nt][rh * 2 + 1] * 0x1p-33;
                size_t oidx = ((size_t)((t * 3 + a) * 256 + b)) * 1024 + e;
                float2 u = *(const float2*)&dout[oidx];
                float2 v = *(const float2*)&g_V[par][(size_t)b * N_ + c];
                float r0 = (float)fmin(1.0, fmax(-1.0, x0 + (double)u.x + (double)v.x));
                float r1 = (float)fmin(1.0, fmax(-1.0, x1 + (double)u.y + (double)v.y));
                *(float2*)&dout[oidx] = make_float2(r0, r1);
                *(float2*)&g_V[par ^ 1][(size_t)b * N_ + c] = make_float2(r0, r1);
                int8_t q00, q01, q02, q10, q11, q12;
                quant3_v(r0, q00, q01, q02);
                quant3_v(r1, q10, q11, q12);
                size_t vidx = (size_t)b * N_ + c;
                *(char2*)&g_VQ[par ^ 1][0][vidx] = make_char2(q00, q10);
                *(char2*)&g_VQ[par ^ 1][1][vidx] = make_char2(q01, q11);
                *(char2*)&g_VQ[par ^ 1][2][vidx] = make_char2(q02, q12);
            }
        }
}

// ------------------------------------------------------------------
extern "C" void kernel_launch(void* const* d_in, const int* in_sizes, int n_in,
                              void* d_out, int out_size) {
    (void)in_sizes; (void)n_in; (void)out_size;
    const float* ento = (const float*)d_in[0];   // [T,B,ENTO]
    const float* v0   = (const float*)d_in[1];   // [A,B,EM]
    const float* w_ih = (const float*)d_in[2];   // [A,EM,IN]
    const float* w_hh = (const float*)d_in[3];   // [A,EM,EM]
    float* out = (float*)d_out;                  // [T,A,B,EM]

    cudaFuncSetAttribute(phase1_gemm, cudaFuncAttributeMaxDynamicSharedMemorySize, SMEM_P1);
    cudaFuncSetAttribute(step_imma,   cudaFuncAttributeMaxDynamicSharedMemorySize, SMEM_ST);

    split_ento <<<dim3(ENTO_ / 256, MROWS), 256>>>(ento);
    split_wento<<<dim3(ENTO_ / 256, N_),    256>>>(w_ih);
    quant_wrec <<<dim3(N_ / 256, N_),       256>>>(w_ih, w_hh);
    quant_v0   <<<dim3(N_ / 256, B_),       256>>>(v0);

    // Phase 1: U = ento @ Wento^T written straight into out (bf16x3 HMMA)
    phase1_gemm<<<dim3(48, 128), 256, SMEM_P1>>>(out);

    // Phase 2: 64 recurrent steps (int8 IMMA, exact s32 accumulation)
    for (int t = 0; t < T_; ++t) {
        step_imma<<<dim3(64, 2), 256, SMEM_ST>>>(t & 1, t, out);
    }
}

// round 13
// speedup vs baseline: 1.5869x; 1.5869x over previous
#include <cuda_runtime.h>
#include <cuda_bf16.h>
#include <cstdint>
#include <cstddef>

#define A_    3
#define T_    64
#define B_    256
#define ENTO_ 2048
#define EM_   1024
#define IN_   4096
#define N_    3072
#define MROWS 16384

// ---------------- device scratch (static globals; no allocation) ----------------
__device__ __nv_bfloat16 g_EntoS [3][(size_t)MROWS * ENTO_];  // ento bf16 splits [row][k]
__device__ __nv_bfloat16 g_WentoS[3][(size_t)N_ * ENTO_];     // W_ento splits   [n][k]
__device__ __nv_bfloat16 g_WrecS [3][(size_t)N_ * N_];        // merged W splits [n][k]
__device__ __nv_bfloat16 g_VS[2][3][B_ * N_];                 // V splits, ping-pong [b][n]
__device__ float         g_V [2][B_ * N_];                    // V fp32, ping-pong  [b][n]

// ---------------- helpers ----------------
__device__ __forceinline__ uint32_t smem_u32(const void* p) {
    uint32_t a;
    asm("{ .reg .u64 t; cvta.to.shared.u64 t, %1; cvt.u32.u64 %0, t; }" : "=r"(a) : "l"(p));
    return a;
}
__device__ __forceinline__ void split3(float f, __nv_bfloat16& h, __nv_bfloat16& m,
                                       __nv_bfloat16& l) {
    h = __float2bfloat16(f);
    float r = f - __bfloat162float(h);
    m = __float2bfloat16(r);
    r = r - __bfloat162float(m);
    l = __float2bfloat16(r);
}

#define LDSM4(r0, r1, r2, r3, addr) \
    asm volatile("ldmatrix.sync.aligned.m8n8.x4.shared.b16 {%0,%1,%2,%3}, [%4];" \
                 : "=r"(r0), "=r"(r1), "=r"(r2), "=r"(r3) : "r"(addr))

#define LDSM2(r0, r1, addr) \
    asm volatile("ldmatrix.sync.aligned.m8n8.x2.shared.b16 {%0,%1}, [%2];" \
                 : "=r"(r0), "=r"(r1) : "r"(addr))

#define MMA16816(d, a, b) \
    asm volatile("mma.sync.aligned.m16n8k16.row.col.f32.bf16.bf16.f32 " \
                 "{%0,%1,%2,%3}, {%4,%5,%6,%7}, {%8,%9}, {%0,%1,%2,%3};" \
                 : "+f"((d)[0]), "+f"((d)[1]), "+f"((d)[2]), "+f"((d)[3]) \
                 : "r"((a)[0]), "r"((a)[1]), "r"((a)[2]), "r"((a)[3]), \
                   "r"((b)[0]), "r"((b)[1]))

#define CPASYNC16(dst, src) \
    asm volatile("cp.async.cg.shared.global [%0], [%1], 16;" :: "r"(dst), "l"(src))

// ---------------- prep (split) kernels ----------------
__global__ void split_ento(const float* __restrict__ ento) {
    int k = blockIdx.x * 256 + threadIdx.x;
    size_t idx = (size_t)blockIdx.y * ENTO_ + k;
    __nv_bfloat16 h, m, l; split3(ento[idx], h, m, l);
    g_EntoS[0][idx] = h; g_EntoS[1][idx] = m; g_EntoS[2][idx] = l;
}
__global__ void split_wento(const float* __restrict__ w_ih) {
    int k = blockIdx.x * 256 + threadIdx.x;
    int n = blockIdx.y;
    float f = w_ih[(size_t)n * IN_ + k];
    __nv_bfloat16 h, m, l; split3(f, h, m, l);
    size_t idx = (size_t)n * ENTO_ + k;
    g_WentoS[0][idx] = h; g_WentoS[1][idx] = m; g_WentoS[2][idx] = l;
}
__global__ void split_wrec(const float* __restrict__ w_ih, const float* __restrict__ w_hh) {
    int k = blockIdx.x * 256 + threadIdx.x;
    int n = blockIdx.y;
    int j = k >> 10, m_ = k & 1023;
    int a = n >> 10;
    float f;
    if (j == a) f = w_hh[(size_t)n * EM_ + m_];
    else {
        int pos = j - (j > a ? 1 : 0);
        f = w_ih[(size_t)n * IN_ + ENTO_ + pos * EM_ + m_];
    }
    __nv_bfloat16 h, m, l; split3(f, h, m, l);
    size_t idx = (size_t)n * N_ + k;
    g_WrecS[0][idx] = h; g_WrecS[1][idx] = m; g_WrecS[2][idx] = l;
}
__global__ void split_v0(const float* __restrict__ v0) {
    int n = blockIdx.x * 256 + threadIdx.x;
    int b = blockIdx.y;
    int j = n >> 10, m_ = n & 1023;
    float f = v0[((size_t)j * B_ + b) * EM_ + m_];
    g_V[0][b * N_ + n] = f;
    __nv_bfloat16 h, m, l; split3(f, h, m, l);
    g_VS[0][0][b * N_ + n] = h;
    g_VS[0][1][b * N_ + n] = m;
    g_VS[0][2][b * N_ + n] = l;
}

// ---------------- Phase 1: bf16x3 HMMA, CTA 128x64 (proven R8 path) ----------------
#define ASPLIT   10240           /* 128*80 */
#define BSPLIT    5120           /* 64*80  */
#define OFFB     30720           /* 3*ASPLIT */
#define BUFSZ    46080
#define SMEM_P1  92160

__global__ __launch_bounds__(256) void phase1_gemm(float* __restrict__ dout) {
    constexpr int S = ENTO_ / 32;
    extern __shared__ char smem[];
    const uint32_t sb = smem_u32(smem);
    const int tid = threadIdx.x, wid = tid >> 5, lane = tid & 31;
    const int warp_m = wid & 3, warp_n = wid >> 2;
    const int n0 = blockIdx.x * 64;
    const int m0 = blockIdx.y * 128;

    float accH[2][4][4], accL[2][4][4], accS[2][4][4];
#pragma unroll
    for (int i = 0; i < 2; ++i)
#pragma unroll
        for (int j = 0; j < 4; ++j)
#pragma unroll
            for (int q = 0; q < 4; ++q) {
                accH[i][j][q] = 0.f; accL[i][j][q] = 0.f; accS[i][j][q] = 0.f;
            }

    auto loadChunk = [&](int s, uint32_t buf) {
        const int kb = s * 32;
#pragma unroll
        for (int i = 0; i < 9; ++i) {
            int u = tid + i * 256;
            const __nv_bfloat16* gp;
            uint32_t sa;
            if (u < 1536) {
                int sp = u >> 9, rem = u & 511, row = rem >> 2, un = rem & 3;
                gp = g_EntoS[sp] + (size_t)(m0 + row) * ENTO_ + kb + un * 8;
                sa = buf + sp * ASPLIT + row * 80 + un * 16;
            } else {
                int v = u - 1536;
                int sp = v >> 8, rem = v & 255, row = rem >> 2, un = rem & 3;
                gp = g_WentoS[sp] + (size_t)(n0 + row) * ENTO_ + kb + un * 8;
                sa = buf + OFFB + sp * BSPLIT + row * 80 + un * 16;
            }
            CPASYNC16(sa, gp);
        }
        asm volatile("cp.async.commit_group;" ::: "memory");
    };

    const int r16 = lane & 15, ahi = (lane >> 4) * 16;
    uint32_t aoff[2];
#pragma unroll
    for (int mt = 0; mt < 2; ++mt)
        aoff[mt] = (uint32_t)(warp_m * 32 + mt * 16 + r16) * 80 + ahi;
    const int bg = lane >> 3, bri = lane & 7;
    uint32_t boff[2];
#pragma unroll
    for (int p = 0; p < 2; ++p)
        boff[p] = (uint32_t)(warp_n * 32 + p * 16 + ((bg >> 1) << 3) + bri) * 80 + (bg & 1) * 16;

    loadChunk(0, sb);

    for (int s = 0; s < S; ++s) {
        if (s + 1 < S) {
            loadChunk(s + 1, sb + (uint32_t)((s + 1) & 1) * BUFSZ);
            asm volatile("cp.async.wait_group 1;" ::: "memory");
        } else {
            asm volatile("cp.async.wait_group 0;" ::: "memory");
        }
        __syncthreads();

        const uint32_t buf = sb + (uint32_t)(s & 1) * BUFSZ;
#pragma unroll
        for (int kk = 0; kk < 2; ++kk) {
            uint32_t af[3][2][4], bf[3][4][2];
#pragma unroll
            for (int sp = 0; sp < 3; ++sp) {
                uint32_t ab = buf + sp * ASPLIT + kk * 32;
#pragma unroll
                for (int mt = 0; mt < 2; ++mt)
                    LDSM4(af[sp][mt][0], af[sp][mt][1], af[sp][mt][2], af[sp][mt][3],
                          ab + aoff[mt]);
                uint32_t bb = buf + OFFB + sp * BSPLIT + kk * 32;
#pragma unroll
                for (int p = 0; p < 2; ++p)
                    LDSM4(bf[sp][2 * p][0], bf[sp][2 * p][1],
                          bf[sp][2 * p + 1][0], bf[sp][2 * p + 1][1],
                          bb + boff[p]);
            }
#pragma unroll
            for (int mt = 0; mt < 2; ++mt)
#pragma unroll
                for (int nt = 0; nt < 4; ++nt) {
                    MMA16816(accH[mt][nt], af[0][mt], bf[0][nt]);
                    MMA16816(accL[mt][nt], af[0][mt], bf[1][nt]);
                    MMA16816(accL[mt][nt], af[1][mt], bf[0][nt]);
                    MMA16816(accL[mt][nt], af[1][mt], bf[1][nt]);
                    MMA16816(accL[mt][nt], af[0][mt], bf[2][nt]);
                    MMA16816(accL[mt][nt], af[2][mt], bf[0][nt]);
                }
        }
        __syncthreads();

        if ((s & 3) == 3) {
#pragma unroll
            for (int mt = 0; mt < 2; ++mt)
#pragma unroll
                for (int nt = 0; nt < 4; ++nt)
#pragma unroll
                    for (int q = 0; q < 4; ++q) {
                        accS[mt][nt][q] += accH[mt][nt][q];
                        accH[mt][nt][q] = 0.f;
                    }
        }
    }

    const int l4 = lane >> 2, l2 = (lane & 3) * 2;
#pragma unroll
    for (int mt = 0; mt < 2; ++mt)
#pragma unroll
        for (int rh = 0; rh < 2; ++rh) {
            const int row = m0 + warp_m * 32 + mt * 16 + rh * 8 + l4;
#pragma unroll
            for (int nt = 0; nt < 4; ++nt) {
                const int c = n0 + warp_n * 32 + nt * 8 + l2;
                const int a = c >> 10, e = c & 1023;
                double x0 = (double)accS[mt][nt][rh * 2 + 0] + (double)accL[mt][nt][rh * 2 + 0];
                double x1 = (double)accS[mt][nt][rh * 2 + 1] + (double)accL[mt][nt][rh * 2 + 1];
                const int tt = row >> 8, b = row & 255;
                size_t oidx = ((size_t)((tt * 3 + a) * 256 + b)) * 1024 + e;
                *(float2*)&dout[oidx] = make_float2((float)x0, (float)x1);
            }
        }
}

// ---------------- Phase 2: bf16x3 HMMA step, CTA 128x48 ----------------
// grid (64, 2) = 128 CTAs -> 86% SM fill (vs 96/65% at tile 64).
// 8 warps 4(m)x2(n); warp tile 32x24 = 2mt x 3nt m16n8 tiles.
// Same accH/accL/accS numerics as phase1 / R8 (proven).
#define BSPLIT_ST  3840          /* 48*80 */
#define OFFB_ST   30720          /* 3*ASPLIT */
#define BUF_ST    42240          /* OFFB_ST + 3*BSPLIT_ST */
#define SMEM_ST   84480

__global__ __launch_bounds__(256) void step_gemm(int par, int t, float* __restrict__ dout) {
    constexpr int S = N_ / 32;   // 96 stages
    extern __shared__ char smem[];
    const uint32_t sb = smem_u32(smem);
    const int tid = threadIdx.x, wid = tid >> 5, lane = tid & 31;
    const int warp_m = wid & 3, warp_n = wid >> 2;
    const int n0 = blockIdx.x * 48;
    const int m0 = blockIdx.y * 128;

    const __nv_bfloat16* __restrict__ Asrc = g_VS[par][0];
    const size_t Astride = (size_t)B_ * N_;
    const __nv_bfloat16* __restrict__ Bsrc = g_WrecS[0];
    const size_t Bstride = (size_t)N_ * N_;

    float accH[2][3][4], accL[2][3][4], accS[2][3][4];
#pragma unroll
    for (int i = 0; i < 2; ++i)
#pragma unroll
        for (int j = 0; j < 3; ++j)
#pragma unroll
            for (int q = 0; q < 4; ++q) {
                accH[i][j][q] = 0.f; accL[i][j][q] = 0.f; accS[i][j][q] = 0.f;
            }

    // loader: A 3sp x 128row x 4 units + B 3sp x 48row x 4 units = 2112 units
    auto loadChunk = [&](int s, uint32_t buf) {
        const int kb = s * 32;
        for (int u = tid; u < 2112; u += 256) {
            const __nv_bfloat16* gp;
            uint32_t sa;
            if (u < 1536) {
                int sp = u >> 9, rem = u & 511, row = rem >> 2, un = rem & 3;
                gp = Asrc + sp * Astride + (size_t)(m0 + row) * N_ + kb + un * 8;
                sa = buf + sp * ASPLIT + row * 80 + un * 16;
            } else {
                int v = u - 1536;
                int sp = v / 192, rem = v - sp * 192, row = rem >> 2, un = rem & 3;
                gp = Bsrc + sp * Bstride + (size_t)(n0 + row) * N_ + kb + un * 8;
                sa = buf + OFFB_ST + sp * BSPLIT_ST + row * 80 + un * 16;
            }
            CPASYNC16(sa, gp);
        }
        asm volatile("cp.async.commit_group;" ::: "memory");
    };

    const int r16 = lane & 15, ahi = (lane >> 4) * 16;
    uint32_t aoff[2];
#pragma unroll
    for (int mt = 0; mt < 2; ++mt)
        aoff[mt] = (uint32_t)(warp_m * 32 + mt * 16 + r16) * 80 + ahi;
    const int bg = lane >> 3, bri = lane & 7;
    // LDSM4 covers nt0/nt1 (16 rows); LDSM2 covers nt2 (8 rows)
    const uint32_t boff4 = (uint32_t)(warp_n * 24 + ((bg >> 1) << 3) + bri) * 80 + (bg & 1) * 16;
    const uint32_t boff2 = (uint32_t)(warp_n * 24 + 16 + bri) * 80 + (bg & 1) * 16;

    loadChunk(0, sb);

    for (int s = 0; s < S; ++s) {
        if (s + 1 < S) {
            loadChunk(s + 1, sb + (uint32_t)((s + 1) & 1) * BUF_ST);
            asm volatile("cp.async.wait_group 1;" ::: "memory");
        } else {
            asm volatile("cp.async.wait_group 0;" ::: "memory");
        }
        __syncthreads();

        const uint32_t buf = sb + (uint32_t)(s & 1) * BUF_ST;
#pragma unroll
        for (int kk = 0; kk < 2; ++kk) {
            uint32_t af[3][2][4], bf[3][3][2];
#pragma unroll
            for (int sp = 0; sp < 3; ++sp) {
                uint32_t ab = buf + sp * ASPLIT + kk * 32;
#pragma unroll
                for (int mt = 0; mt < 2; ++mt)
                    LDSM4(af[sp][mt][0], af[sp][mt][1], af[sp][mt][2], af[sp][mt][3],
                          ab + aoff[mt]);
                uint32_t bb = buf + OFFB_ST + sp * BSPLIT_ST + kk * 32;
                LDSM4(bf[sp][0][0], bf[sp][0][1], bf[sp][1][0], bf[sp][1][1], bb + boff4);
                LDSM2(bf[sp][2][0], bf[sp][2][1], bb + boff2);
            }
#pragma unroll
            for (int mt = 0; mt < 2; ++mt)
#pragma unroll
                for (int nt = 0; nt < 3; ++nt) {
                    MMA16816(accH[mt][nt], af[0][mt], bf[0][nt]);
                    MMA16816(accL[mt][nt], af[0][mt], bf[1][nt]);
                    MMA16816(accL[mt][nt], af[1][mt], bf[0][nt]);
                    MMA16816(accL[mt][nt], af[1][mt], bf[1][nt]);
                    MMA16816(accL[mt][nt], af[0][mt], bf[2][nt]);
                    MMA16816(accL[mt][nt], af[2][mt], bf[0][nt]);
                }
        }
        __syncthreads();

        if ((s & 3) == 3) {
#pragma unroll
            for (int mt = 0; mt < 2; ++mt)
#pragma unroll
                for (int nt = 0; nt < 3; ++nt)
#pragma unroll
                    for (int q = 0; q < 4; ++q) {
                        accS[mt][nt][q] += accH[mt][nt][q];
                        accH[mt][nt][q] = 0.f;
                    }
        }
    }

    // ---- epilogue: combine, clip, write h, produce next-step splits ----
    const int l4 = lane >> 2, l2 = (lane & 3) * 2;
#pragma unroll
    for (int mt = 0; mt < 2; ++mt)
#pragma unroll
        for (int rh = 0; rh < 2; ++rh) {
            const int b = m0 + warp_m * 32 + mt * 16 + rh * 8 + l4;   // batch row
#pragma unroll
            for (int nt = 0; nt < 3; ++nt) {
                const int c = n0 + warp_n * 24 + nt * 8 + l2;
                const int a = c >> 10, e = c & 1023;
                double x0 = (double)accS[mt][nt][rh * 2 + 0] + (double)accL[mt][nt][rh * 2 + 0];
                double x1 = (double)accS[mt][nt][rh * 2 + 1] + (double)accL[mt][nt][rh * 2 + 1];
                size_t oidx = ((size_t)((t * 3 + a) * 256 + b)) * 1024 + e;
                float2 u = *(const float2*)&dout[oidx];
                float2 v = *(const float2*)&g_V[par][(size_t)b * N_ + c];
                float r0 = (float)fmin(1.0, fmax(-1.0, x0 + (double)u.x + (double)v.x));
                float r1 = (float)fmin(1.0, fmax(-1.0, x1 + (double)u.y + (double)v.y));
                *(float2*)&dout[oidx] = make_float2(r0, r1);
                *(float2*)&g_V[par ^ 1][(size_t)b * N_ + c] = make_float2(r0, r1);
                __nv_bfloat16 h0, mm0, l0, h1, mm1, l1;
                split3(r0, h0, mm0, l0);
                split3(r1, h1, mm1, l1);
                size_t vidx = (size_t)b * N_ + c;
                *(__nv_bfloat162*)&g_VS[par ^ 1][0][vidx] = __nv_bfloat162{h0, h1};
                *(__nv_bfloat162*)&g_VS[par ^ 1][1][vidx] = __nv_bfloat162{mm0, mm1};
                *(__nv_bfloat162*)&g_VS[par ^ 1][2][vidx] = __nv_bfloat162{l0, l1};
            }
        }
}

// ------------------------------------------------------------------
extern "C" void kernel_launch(void* const* d_in, const int* in_sizes, int n_in,
                              void* d_out, int out_size) {
    (void)in_sizes; (void)n_in; (void)out_size;
    const float* ento = (const float*)d_in[0];   // [T,B,ENTO]
    const float* v0   = (const float*)d_in[1];   // [A,B,EM]
    const float* w_ih = (const float*)d_in[2];   // [A,EM,IN]
    const float* w_hh = (const float*)d_in[3];   // [A,EM,EM]
    float* out = (float*)d_out;                  // [T,A,B,EM]

    cudaFuncSetAttribute(phase1_gemm, cudaFuncAttributeMaxDynamicSharedMemorySize, SMEM_P1);
    cudaFuncSetAttribute(step_gemm,   cudaFuncAttributeMaxDynamicSharedMemorySize, SMEM_ST);

    split_ento <<<dim3(ENTO_ / 256, MROWS), 256>>>(ento);
    split_wento<<<dim3(ENTO_ / 256, N_),    256>>>(w_ih);
    split_wrec <<<dim3(N_ / 256, N_),       256>>>(w_ih, w_hh);
    split_v0   <<<dim3(N_ / 256, B_),       256>>>(v0);

    // Phase 1: U = ento @ Wento^T written straight into out (bf16x3 HMMA)
    phase1_gemm<<<dim3(48, 128), 256, SMEM_P1>>>(out);

    // Phase 2: 64 recurrent steps (bf16x3 HMMA, 128 CTAs/step)
    for (int t = 0; t < T_; ++t) {
        step_gemm<<<dim3(64, 2), 256, SMEM_ST>>>(t & 1, t, out);
    }
}

// round 14
// speedup vs baseline: 1.8337x; 1.1555x over previous
#include <cuda_runtime.h>
#include <cuda_bf16.h>
#include <cstdint>
#include <cstddef>

#define A_    3
#define T_    64
#define B_    256
#define ENTO_ 2048
#define EM_   1024
#define IN_   4096
#define N_    3072
#define MROWS 16384

// ---------------- device scratch (static globals; no allocation) ----------------
__device__ __nv_bfloat16 g_EntoS [3][(size_t)MROWS * ENTO_];  // ento bf16 splits [row][k]
__device__ __nv_bfloat16 g_WentoS[3][(size_t)N_ * ENTO_];     // W_ento splits   [n][k]
__device__ __nv_bfloat16 g_WrecS [3][(size_t)N_ * N_];        // merged W splits [n][k]
__device__ __nv_bfloat16 g_VS[2][3][B_ * N_];                 // V splits, ping-pong [b][n]
__device__ float         g_V [2][B_ * N_];                    // V fp32, ping-pong  [b][n]

// ---------------- helpers ----------------
__device__ __forceinline__ uint32_t smem_u32(const void* p) {
    uint32_t a;
    asm("{ .reg .u64 t; cvta.to.shared.u64 t, %1; cvt.u32.u64 %0, t; }" : "=r"(a) : "l"(p));
    return a;
}
__device__ __forceinline__ void split3(float f, __nv_bfloat16& h, __nv_bfloat16& m,
                                       __nv_bfloat16& l) {
    h = __float2bfloat16(f);
    float r = f - __bfloat162float(h);
    m = __float2bfloat16(r);
    r = r - __bfloat162float(m);
    l = __float2bfloat16(r);
}

#define LDSM4(r0, r1, r2, r3, addr) \
    asm volatile("ldmatrix.sync.aligned.m8n8.x4.shared.b16 {%0,%1,%2,%3}, [%4];" \
                 : "=r"(r0), "=r"(r1), "=r"(r2), "=r"(r3) : "r"(addr))

#define LDSM2(r0, r1, addr) \
    asm volatile("ldmatrix.sync.aligned.m8n8.x2.shared.b16 {%0,%1}, [%2];" \
                 : "=r"(r0), "=r"(r1) : "r"(addr))

#define MMA16816(d, a, b) \
    asm volatile("mma.sync.aligned.m16n8k16.row.col.f32.bf16.bf16.f32 " \
                 "{%0,%1,%2,%3}, {%4,%5,%6,%7}, {%8,%9}, {%0,%1,%2,%3};" \
                 : "+f"((d)[0]), "+f"((d)[1]), "+f"((d)[2]), "+f"((d)[3]) \
                 : "r"((a)[0]), "r"((a)[1]), "r"((a)[2]), "r"((a)[3]), \
                   "r"((b)[0]), "r"((b)[1]))

#define CPASYNC16(dst, src) \
    asm volatile("cp.async.cg.shared.global [%0], [%1], 16;" :: "r"(dst), "l"(src))

// ---------------- prep (split) kernels ----------------
__global__ void split_ento(const float* __restrict__ ento) {
    int k = blockIdx.x * 256 + threadIdx.x;
    size_t idx = (size_t)blockIdx.y * ENTO_ + k;
    __nv_bfloat16 h, m, l; split3(ento[idx], h, m, l);
    g_EntoS[0][idx] = h; g_EntoS[1][idx] = m; g_EntoS[2][idx] = l;
}
__global__ void split_wento(const float* __restrict__ w_ih) {
    int k = blockIdx.x * 256 + threadIdx.x;
    int n = blockIdx.y;
    float f = w_ih[(size_t)n * IN_ + k];
    __nv_bfloat16 h, m, l; split3(f, h, m, l);
    size_t idx = (size_t)n * ENTO_ + k;
    g_WentoS[0][idx] = h; g_WentoS[1][idx] = m; g_WentoS[2][idx] = l;
}
__global__ void split_wrec(const float* __restrict__ w_ih, const float* __restrict__ w_hh) {
    int k = blockIdx.x * 256 + threadIdx.x;
    int n = blockIdx.y;
    int j = k >> 10, m_ = k & 1023;
    int a = n >> 10;
    float f;
    if (j == a) f = w_hh[(size_t)n * EM_ + m_];
    else {
        int pos = j - (j > a ? 1 : 0);
        f = w_ih[(size_t)n * IN_ + ENTO_ + pos * EM_ + m_];
    }
    __nv_bfloat16 h, m, l; split3(f, h, m, l);
    size_t idx = (size_t)n * N_ + k;
    g_WrecS[0][idx] = h; g_WrecS[1][idx] = m; g_WrecS[2][idx] = l;
}
__global__ void split_v0(const float* __restrict__ v0) {
    int n = blockIdx.x * 256 + threadIdx.x;
    int b = blockIdx.y;
    int j = n >> 10, m_ = n & 1023;
    float f = v0[((size_t)j * B_ + b) * EM_ + m_];
    g_V[0][b * N_ + n] = f;
    __nv_bfloat16 h, m, l; split3(f, h, m, l);
    g_VS[0][0][b * N_ + n] = h;
    g_VS[0][1][b * N_ + n] = m;
    g_VS[0][2][b * N_ + n] = l;
}

// ---------------- k64-staged bf16x3 HMMA kernels ----------------
// Rows hold 64 k-elems = 128B, padded to 144B stride (banks 4r mod 32:
// conflict-free for ldmatrix and cp.async stores).
// Drain accH -> accS every 2 stages = k128 (bit-identical to the k32/4-stage
// schedule: same 8 k16-granule MMA sequence per drain window).
#define AS64      18432          /* 128*144 A-split bytes */
#define OFFB64    55296          /* 3*AS64 */

// Phase 1: CTA 128x64, grid (48, 128)
#define BS64_P1    9216          /* 64*144 */
#define BUF_P1    82944          /* OFFB64 + 3*BS64_P1 */
#define SMEM_P1  165888

// Phase 2: CTA 128x48, grid (64, 2) = 128 CTAs
#define BS64_ST    6912          /* 48*144 */
#define BUF_ST    76032          /* OFFB64 + 3*BS64_ST */
#define SMEM_ST  152064

__global__ __launch_bounds__(256) void phase1_gemm(float* __restrict__ dout) {
    constexpr int S = ENTO_ / 64;   // 32 stages
    extern __shared__ char smem[];
    const uint32_t sb = smem_u32(smem);
    const int tid = threadIdx.x, wid = tid >> 5, lane = tid & 31;
    const int warp_m = wid & 3, warp_n = wid >> 2;
    const int n0 = blockIdx.x * 64;
    const int m0 = blockIdx.y * 128;

    float accH[2][4][4], accL[2][4][4], accS[2][4][4];
#pragma unroll
    for (int i = 0; i < 2; ++i)
#pragma unroll
        for (int j = 0; j < 4; ++j)
#pragma unroll
            for (int q = 0; q < 4; ++q) {
                accH[i][j][q] = 0.f; accL[i][j][q] = 0.f; accS[i][j][q] = 0.f;
            }

    // loader: A 3sp x 128row x 8un + B 3sp x 64row x 8un = 4608 units, 18/thread
    auto loadChunk = [&](int s, uint32_t buf) {
        const int kb = s * 64;
#pragma unroll
        for (int i = 0; i < 18; ++i) {
            int u = tid + i * 256;
            const __nv_bfloat16* gp;
            uint32_t sa;
            if (u < 3072) {
                int sp = u >> 10, rem = u & 1023, row = rem >> 3, un = rem & 7;
                gp = g_EntoS[sp] + (size_t)(m0 + row) * ENTO_ + kb + un * 8;
                sa = buf + sp * AS64 + row * 144 + un * 16;
            } else {
                int v = u - 3072;
                int sp = v >> 9, rem = v & 511, row = rem >> 3, un = rem & 7;
                gp = g_WentoS[sp] + (size_t)(n0 + row) * ENTO_ + kb + un * 8;
                sa = buf + OFFB64 + sp * BS64_P1 + row * 144 + un * 16;
            }
            CPASYNC16(sa, gp);
        }
        asm volatile("cp.async.commit_group;" ::: "memory");
    };

    const int r16 = lane & 15, ahi = (lane >> 4) * 16;
    uint32_t aoff[2];
#pragma unroll
    for (int mt = 0; mt < 2; ++mt)
        aoff[mt] = (uint32_t)(warp_m * 32 + mt * 16 + r16) * 144 + ahi;
    const int bg = lane >> 3, bri = lane & 7;
    uint32_t boff[2];
#pragma unroll
    for (int p = 0; p < 2; ++p)
        boff[p] = (uint32_t)(warp_n * 32 + p * 16 + ((bg >> 1) << 3) + bri) * 144 + (bg & 1) * 16;

    loadChunk(0, sb);

    for (int s = 0; s < S; ++s) {
        if (s + 1 < S) {
            loadChunk(s + 1, sb + (uint32_t)((s + 1) & 1) * BUF_P1);
            asm volatile("cp.async.wait_group 1;" ::: "memory");
        } else {
            asm volatile("cp.async.wait_group 0;" ::: "memory");
        }
        __syncthreads();

        const uint32_t buf = sb + (uint32_t)(s & 1) * BUF_P1;
#pragma unroll
        for (int kk = 0; kk < 4; ++kk) {
            uint32_t af[3][2][4], bf[3][4][2];
#pragma unroll
            for (int sp = 0; sp < 3; ++sp) {
                uint32_t ab = buf + sp * AS64 + kk * 32;
#pragma unroll
                for (int mt = 0; mt < 2; ++mt)
                    LDSM4(af[sp][mt][0], af[sp][mt][1], af[sp][mt][2], af[sp][mt][3],
                          ab + aoff[mt]);
                uint32_t bb = buf + OFFB64 + sp * BS64_P1 + kk * 32;
#pragma unroll
                for (int p = 0; p < 2; ++p)
                    LDSM4(bf[sp][2 * p][0], bf[sp][2 * p][1],
                          bf[sp][2 * p + 1][0], bf[sp][2 * p + 1][1],
                          bb + boff[p]);
            }
#pragma unroll
            for (int mt = 0; mt < 2; ++mt)
#pragma unroll
                for (int nt = 0; nt < 4; ++nt) {
                    MMA16816(accH[mt][nt], af[0][mt], bf[0][nt]);
                    MMA16816(accL[mt][nt], af[0][mt], bf[1][nt]);
                    MMA16816(accL[mt][nt], af[1][mt], bf[0][nt]);
                    MMA16816(accL[mt][nt], af[1][mt], bf[1][nt]);
                    MMA16816(accL[mt][nt], af[0][mt], bf[2][nt]);
                    MMA16816(accL[mt][nt], af[2][mt], bf[0][nt]);
                }
        }
        __syncthreads();

        if (s & 1) {   // k128 drain period (same as before)
#pragma unroll
            for (int mt = 0; mt < 2; ++mt)
#pragma unroll
                for (int nt = 0; nt < 4; ++nt)
#pragma unroll
                    for (int q = 0; q < 4; ++q) {
                        accS[mt][nt][q] += accH[mt][nt][q];
                        accH[mt][nt][q] = 0.f;
                    }
        }
    }

    const int l4 = lane >> 2, l2 = (lane & 3) * 2;
#pragma unroll
    for (int mt = 0; mt < 2; ++mt)
#pragma unroll
        for (int rh = 0; rh < 2; ++rh) {
            const int row = m0 + warp_m * 32 + mt * 16 + rh * 8 + l4;
#pragma unroll
            for (int nt = 0; nt < 4; ++nt) {
                const int c = n0 + warp_n * 32 + nt * 8 + l2;
                const int a = c >> 10, e = c & 1023;
                double x0 = (double)accS[mt][nt][rh * 2 + 0] + (double)accL[mt][nt][rh * 2 + 0];
                double x1 = (double)accS[mt][nt][rh * 2 + 1] + (double)accL[mt][nt][rh * 2 + 1];
                const int tt = row >> 8, b = row & 255;
                size_t oidx = ((size_t)((tt * 3 + a) * 256 + b)) * 1024 + e;
                *(float2*)&dout[oidx] = make_float2((float)x0, (float)x1);
            }
        }
}

__global__ __launch_bounds__(256) void step_gemm(int par, int t, float* __restrict__ dout) {
    constexpr int S = N_ / 64;   // 48 stages
    extern __shared__ char smem[];
    const uint32_t sb = smem_u32(smem);
    const int tid = threadIdx.x, wid = tid >> 5, lane = tid & 31;
    const int warp_m = wid & 3, warp_n = wid >> 2;
    const int n0 = blockIdx.x * 48;
    const int m0 = blockIdx.y * 128;

    const __nv_bfloat16* __restrict__ Asrc = g_VS[par][0];
    const size_t Astride = (size_t)B_ * N_;
    const __nv_bfloat16* __restrict__ Bsrc = g_WrecS[0];
    const size_t Bstride = (size_t)N_ * N_;

    float accH[2][3][4], accL[2][3][4], accS[2][3][4];
#pragma unroll
    for (int i = 0; i < 2; ++i)
#pragma unroll
        for (int j = 0; j < 3; ++j)
#pragma unroll
            for (int q = 0; q < 4; ++q) {
                accH[i][j][q] = 0.f; accL[i][j][q] = 0.f; accS[i][j][q] = 0.f;
            }

    // loader: A 3sp x 128row x 8un (3072) + B 3sp x 48row x 8un (1152) = 4224 units
    auto loadChunk = [&](int s, uint32_t buf) {
        const int kb = s * 64;
        for (int u = tid; u < 4224; u += 256) {
            const __nv_bfloat16* gp;
            uint32_t sa;
            if (u < 3072) {
                int sp = u >> 10, rem = u & 1023, row = rem >> 3, un = rem & 7;
                gp = Asrc + sp * Astride + (size_t)(m0 + row) * N_ + kb + un * 8;
                sa = buf + sp * AS64 + row * 144 + un * 16;
            } else {
                int v = u - 3072;
                int sp = v / 384, rem = v - sp * 384, row = rem >> 3, un = rem & 7;
                gp = Bsrc + sp * Bstride + (size_t)(n0 + row) * N_ + kb + un * 8;
                sa = buf + OFFB64 + sp * BS64_ST + row * 144 + un * 16;
            }
            CPASYNC16(sa, gp);
        }
        asm volatile("cp.async.commit_group;" ::: "memory");
    };

    const int r16 = lane & 15, ahi = (lane >> 4) * 16;
    uint32_t aoff[2];
#pragma unroll
    for (int mt = 0; mt < 2; ++mt)
        aoff[mt] = (uint32_t)(warp_m * 32 + mt * 16 + r16) * 144 + ahi;
    const int bg = lane >> 3, bri = lane & 7;
    const uint32_t boff4 = (uint32_t)(warp_n * 24 + ((bg >> 1) << 3) + bri) * 144 + (bg & 1) * 16;
    const uint32_t boff2 = (uint32_t)(warp_n * 24 + 16 + bri) * 144 + (bg & 1) * 16;

    loadChunk(0, sb);

    for (int s = 0; s < S; ++s) {
        if (s + 1 < S) {
            loadChunk(s + 1, sb + (uint32_t)((s + 1) & 1) * BUF_ST);
            asm volatile("cp.async.wait_group 1;" ::: "memory");
        } else {
            asm volatile("cp.async.wait_group 0;" ::: "memory");
        }
        __syncthreads();

        const uint32_t buf = sb + (uint32_t)(s & 1) * BUF_ST;
#pragma unroll
        for (int kk = 0; kk < 4; ++kk) {
            uint32_t af[3][2][4], bf[3][3][2];
#pragma unroll
            for (int sp = 0; sp < 3; ++sp) {
                uint32_t ab = buf + sp * AS64 + kk * 32;
#pragma unroll
                for (int mt = 0; mt < 2; ++mt)
                    LDSM4(af[sp][mt][0], af[sp][mt][1], af[sp][mt][2], af[sp][mt][3],
                          ab + aoff[mt]);
                uint32_t bb = buf + OFFB64 + sp * BS64_ST + kk * 32;
                LDSM4(bf[sp][0][0], bf[sp][0][1], bf[sp][1][0], bf[sp][1][1], bb + boff4);
                LDSM2(bf[sp][2][0], bf[sp][2][1], bb + boff2);
            }
#pragma unroll
            for (int mt = 0; mt < 2; ++mt)
#pragma unroll
                for (int nt = 0; nt < 3; ++nt) {
                    MMA16816(accH[mt][nt], af[0][mt], bf[0][nt]);
                    MMA16816(accL[mt][nt], af[0][mt], bf[1][nt]);
                    MMA16816(accL[mt][nt], af[1][mt], bf[0][nt]);
                    MMA16816(accL[mt][nt], af[1][mt], bf[1][nt]);
                    MMA16816(accL[mt][nt], af[0][mt], bf[2][nt]);
                    MMA16816(accL[mt][nt], af[2][mt], bf[0][nt]);
                }
        }
        __syncthreads();

        if (s & 1) {   // k128 drain period
#pragma unroll
            for (int mt = 0; mt < 2; ++mt)
#pragma unroll
                for (int nt = 0; nt < 3; ++nt)
#pragma unroll
                    for (int q = 0; q < 4; ++q) {
                        accS[mt][nt][q] += accH[mt][nt][q];
                        accH[mt][nt][q] = 0.f;
                    }
        }
    }

    // ---- epilogue: combine, clip, write h, produce next-step splits ----
    const int l4 = lane >> 2, l2 = (lane & 3) * 2;
#pragma unroll
    for (int mt = 0; mt < 2; ++mt)
#pragma unroll
        for (int rh = 0; rh < 2; ++rh) {
            const int b = m0 + warp_m * 32 + mt * 16 + rh * 8 + l4;   // batch row
#pragma unroll
            for (int nt = 0; nt < 3; ++nt) {
                const int c = n0 + warp_n * 24 + nt * 8 + l2;
                const int a = c >> 10, e = c & 1023;
                double x0 = (double)accS[mt][nt][rh * 2 + 0] + (double)accL[mt][nt][rh * 2 + 0];
                double x1 = (double)accS[mt][nt][rh * 2 + 1] + (double)accL[mt][nt][rh * 2 + 1];
                size_t oidx = ((size_t)((t * 3 + a) * 256 + b)) * 1024 + e;
                float2 u = *(const float2*)&dout[oidx];
                float2 v = *(const float2*)&g_V[par][(size_t)b * N_ + c];
                float r0 = (float)fmin(1.0, fmax(-1.0, x0 + (double)u.x + (double)v.x));
                float r1 = (float)fmin(1.0, fmax(-1.0, x1 + (double)u.y + (double)v.y));
                *(float2*)&dout[oidx] = make_float2(r0, r1);
                *(float2*)&g_V[par ^ 1][(size_t)b * N_ + c] = make_float2(r0, r1);
                __nv_bfloat16 h0, mm0, l0, h1, mm1, l1;
                split3(r0, h0, mm0, l0);
                split3(r1, h1, mm1, l1);
                size_t vidx = (size_t)b * N_ + c;
                *(__nv_bfloat162*)&g_VS[par ^ 1][0][vidx] = __nv_bfloat162{h0, h1};
                *(__nv_bfloat162*)&g_VS[par ^ 1][1][vidx] = __nv_bfloat162{mm0, mm1};
                *(__nv_bfloat162*)&g_VS[par ^ 1][2][vidx] = __nv_bfloat162{l0, l1};
            }
        }
}

// ------------------------------------------------------------------
extern "C" void kernel_launch(void* const* d_in, const int* in_sizes, int n_in,
                              void* d_out, int out_size) {
    (void)in_sizes; (void)n_in; (void)out_size;
    const float* ento = (const float*)d_in[0];   // [T,B,ENTO]
    const float* v0   = (const float*)d_in[1];   // [A,B,EM]
    const float* w_ih = (const float*)d_in[2];   // [A,EM,IN]
    const float* w_hh = (const float*)d_in[3];   // [A,EM,EM]
    float* out = (float*)d_out;                  // [T,A,B,EM]

    cudaFuncSetAttribute(phase1_gemm, cudaFuncAttributeMaxDynamicSharedMemorySize, SMEM_P1);
    cudaFuncSetAttribute(step_gemm,   cudaFuncAttributeMaxDynamicSharedMemorySize, SMEM_ST);

    // Launch order puts phase1_gemm 4th — the slot the bench's ncu capture
    // has hit every round — so next profile shows GEMM internals.
    split_ento <<<dim3(ENTO_ / 256, MROWS), 256>>>(ento);
    split_wento<<<dim3(ENTO_ / 256, N_),    256>>>(w_ih);
    split_v0   <<<dim3(N_ / 256, B_),       256>>>(v0);

    // Phase 1: U = ento @ Wento^T written straight into out (bf16x3 HMMA)
    phase1_gemm<<<dim3(48, 128), 256, SMEM_P1>>>(out);

    // Wrec splits needed only before step 0
    split_wrec <<<dim3(N_ / 256, N_),       256>>>(w_ih, w_hh);

    // Phase 2: 64 recurrent steps (bf16x3 HMMA, 128 CTAs/step)
    for (int t = 0; t < T_; ++t) {
        step_gemm<<<dim3(64, 2), 256, SMEM_ST>>>(t & 1, t, out);
    }
}

// round 15
// speedup vs baseline: 1.9069x; 1.0399x over previous
#include <cuda_runtime.h>
#include <cuda_bf16.h>
#include <cstdint>
#include <cstddef>

#define A_    3
#define T_    64
#define B_    256
#define ENTO_ 2048
#define EM_   1024
#define IN_   4096
#define N_    3072
#define MROWS 16384

// ---------------- device scratch (static globals; no allocation) ----------------
__device__ __nv_bfloat16 g_EntoS [3][(size_t)MROWS * ENTO_];  // ento bf16 splits [row][k]
__device__ __nv_bfloat16 g_WentoS[3][(size_t)N_ * ENTO_];     // W_ento splits   [n][k]
__device__ __nv_bfloat16 g_WrecS [3][(size_t)N_ * N_];        // merged W splits [n][k]
__device__ __nv_bfloat16 g_VS[2][3][B_ * N_];                 // V splits, ping-pong [b][n]
__device__ float         g_V [2][B_ * N_];                    // V fp32, ping-pong  [b][n]
__device__ unsigned      g_bar;                               // grid barrier counter

// ---------------- helpers ----------------
__device__ __forceinline__ uint32_t smem_u32(const void* p) {
    uint32_t a;
    asm("{ .reg .u64 t; cvta.to.shared.u64 t, %1; cvt.u32.u64 %0, t; }" : "=r"(a) : "l"(p));
    return a;
}
__device__ __forceinline__ void split3(float f, __nv_bfloat16& h, __nv_bfloat16& m,
                                       __nv_bfloat16& l) {
    h = __float2bfloat16(f);
    float r = f - __bfloat162float(h);
    m = __float2bfloat16(r);
    r = r - __bfloat162float(m);
    l = __float2bfloat16(r);
}

#define LDSM4(r0, r1, r2, r3, addr) \
    asm volatile("ldmatrix.sync.aligned.m8n8.x4.shared.b16 {%0,%1,%2,%3}, [%4];" \
                 : "=r"(r0), "=r"(r1), "=r"(r2), "=r"(r3) : "r"(addr))

#define LDSM2(r0, r1, addr) \
    asm volatile("ldmatrix.sync.aligned.m8n8.x2.shared.b16 {%0,%1}, [%2];" \
                 : "=r"(r0), "=r"(r1) : "r"(addr))

#define MMA16816(d, a, b) \
    asm volatile("mma.sync.aligned.m16n8k16.row.col.f32.bf16.bf16.f32 " \
                 "{%0,%1,%2,%3}, {%4,%5,%6,%7}, {%8,%9}, {%0,%1,%2,%3};" \
                 : "+f"((d)[0]), "+f"((d)[1]), "+f"((d)[2]), "+f"((d)[3]) \
                 : "r"((a)[0]), "r"((a)[1]), "r"((a)[2]), "r"((a)[3]), \
                   "r"((b)[0]), "r"((b)[1]))

#define CPASYNC16(dst, src) \
    asm volatile("cp.async.cg.shared.global [%0], [%1], 16;" :: "r"(dst), "l"(src))

// ---------------- prep (split) kernels ----------------
__global__ void split_ento(const float* __restrict__ ento) {
    int k = blockIdx.x * 256 + threadIdx.x;
    size_t idx = (size_t)blockIdx.y * ENTO_ + k;
    __nv_bfloat16 h, m, l; split3(ento[idx], h, m, l);
    g_EntoS[0][idx] = h; g_EntoS[1][idx] = m; g_EntoS[2][idx] = l;
}
__global__ void split_wento(const float* __restrict__ w_ih) {
    int k = blockIdx.x * 256 + threadIdx.x;
    int n = blockIdx.y;
    float f = w_ih[(size_t)n * IN_ + k];
    __nv_bfloat16 h, m, l; split3(f, h, m, l);
    size_t idx = (size_t)n * ENTO_ + k;
    g_WentoS[0][idx] = h; g_WentoS[1][idx] = m; g_WentoS[2][idx] = l;
}
__global__ void split_wrec(const float* __restrict__ w_ih, const float* __restrict__ w_hh) {
    int k = blockIdx.x * 256 + threadIdx.x;
    int n = blockIdx.y;
    int j = k >> 10, m_ = k & 1023;
    int a = n >> 10;
    float f;
    if (j == a) f = w_hh[(size_t)n * EM_ + m_];
    else {
        int pos = j - (j > a ? 1 : 0);
        f = w_ih[(size_t)n * IN_ + ENTO_ + pos * EM_ + m_];
    }
    __nv_bfloat16 h, m, l; split3(f, h, m, l);
    size_t idx = (size_t)n * N_ + k;
    g_WrecS[0][idx] = h; g_WrecS[1][idx] = m; g_WrecS[2][idx] = l;
}
__global__ void split_v0(const float* __restrict__ v0) {
    int n = blockIdx.x * 256 + threadIdx.x;
    int b = blockIdx.y;
    int j = n >> 10, m_ = n & 1023;
    float f = v0[((size_t)j * B_ + b) * EM_ + m_];
    g_V[0][b * N_ + n] = f;
    __nv_bfloat16 h, m, l; split3(f, h, m, l);
    g_VS[0][0][b * N_ + n] = h;
    g_VS[0][1][b * N_ + n] = m;
    g_VS[0][2][b * N_ + n] = l;
}
__global__ void zero_bar() { g_bar = 0; }

// ---------------- k64-staged bf16x3 HMMA kernels ----------------
#define AS64      18432          /* 128*144 A-split bytes */
#define OFFB64    55296          /* 3*AS64 */

// Phase 1: CTA 128x96, 384 threads (12 warps 4m x 3n), grid (32, 128)
#define BS64_P1   13824          /* 96*144 */
#define BUF_P1    96768          /* OFFB64 + 3*BS64_P1 */
#define SMEM_P1  193536

// Phase 2: CTA 128x48, 256 threads, grid (64, 2) = 128 CTAs, persistent
#define BS64_ST    6912          /* 48*144 */
#define BUF_ST    76032          /* OFFB64 + 3*BS64_ST */
#define SMEM_ST  152064

__global__ __launch_bounds__(384) void phase1_gemm(float* __restrict__ dout) {
    constexpr int S = ENTO_ / 64;   // 32 stages
    extern __shared__ char smem[];
    const uint32_t sb = smem_u32(smem);
    const int tid = threadIdx.x, wid = tid >> 5, lane = tid & 31;
    const int warp_m = wid & 3, warp_n = wid >> 2;   // 4m x 3n
    const int n0 = blockIdx.x * 96;
    const int m0 = blockIdx.y * 128;

    float accH[2][4][4], accL[2][4][4], accS[2][4][4];
#pragma unroll
    for (int i = 0; i < 2; ++i)
#pragma unroll
        for (int j = 0; j < 4; ++j)
#pragma unroll
            for (int q = 0; q < 4; ++q) {
                accH[i][j][q] = 0.f; accL[i][j][q] = 0.f; accS[i][j][q] = 0.f;
            }

    // loader: A 3sp x 128row x 8un (3072) + B 3sp x 96row x 8un (2304) = 5376 = 14/thread
    auto loadChunk = [&](int s, uint32_t buf) {
        const int kb = s * 64;
#pragma unroll
        for (int i = 0; i < 14; ++i) {
            int u = tid + i * 384;
            const __nv_bfloat16* gp;
            uint32_t sa;
            if (u < 3072) {
                int sp = u >> 10, rem = u & 1023, row = rem >> 3, un = rem & 7;
                gp = g_EntoS[sp] + (size_t)(m0 + row) * ENTO_ + kb + un * 8;
                sa = buf + sp * AS64 + row * 144 + un * 16;
            } else {
                int v = u - 3072;
                int sp = v / 768, rem = v - sp * 768, row = rem >> 3, un = rem & 7;
                gp = g_WentoS[sp] + (size_t)(n0 + row) * ENTO_ + kb + un * 8;
                sa = buf + OFFB64 + sp * BS64_P1 + row * 144 + un * 16;
            }
            CPASYNC16(sa, gp);
        }
        asm volatile("cp.async.commit_group;" ::: "memory");
    };

    const int r16 = lane & 15, ahi = (lane >> 4) * 16;
    uint32_t aoff[2];
#pragma unroll
    for (int mt = 0; mt < 2; ++mt)
        aoff[mt] = (uint32_t)(warp_m * 32 + mt * 16 + r16) * 144 + ahi;
    const int bg = lane >> 3, bri = lane & 7;
    uint32_t boff[2];
#pragma unroll
    for (int p = 0; p < 2; ++p)
        boff[p] = (uint32_t)(warp_n * 32 + p * 16 + ((bg >> 1) << 3) + bri) * 144 + (bg & 1) * 16;

    loadChunk(0, sb);

    for (int s = 0; s < S; ++s) {
        if (s + 1 < S) {
            loadChunk(s + 1, sb + (uint32_t)((s + 1) & 1) * BUF_P1);
            asm volatile("cp.async.wait_group 1;" ::: "memory");
        } else {
            asm volatile("cp.async.wait_group 0;" ::: "memory");
        }
        __syncthreads();

        const uint32_t buf = sb + (uint32_t)(s & 1) * BUF_P1;
#pragma unroll
        for (int kk = 0; kk < 4; ++kk) {
            uint32_t af[3][2][4], bf[3][4][2];
#pragma unroll
            for (int sp = 0; sp < 3; ++sp) {
                uint32_t ab = buf + sp * AS64 + kk * 32;
#pragma unroll
                for (int mt = 0; mt < 2; ++mt)
                    LDSM4(af[sp][mt][0], af[sp][mt][1], af[sp][mt][2], af[sp][mt][3],
                          ab + aoff[mt]);
                uint32_t bb = buf + OFFB64 + sp * BS64_P1 + kk * 32;
#pragma unroll
                for (int p = 0; p < 2; ++p)
                    LDSM4(bf[sp][2 * p][0], bf[sp][2 * p][1],
                          bf[sp][2 * p + 1][0], bf[sp][2 * p + 1][1],
                          bb + boff[p]);
            }
#pragma unroll
            for (int mt = 0; mt < 2; ++mt)
#pragma unroll
                for (int nt = 0; nt < 4; ++nt) {
                    MMA16816(accH[mt][nt], af[0][mt], bf[0][nt]);
                    MMA16816(accL[mt][nt], af[0][mt], bf[1][nt]);
                    MMA16816(accL[mt][nt], af[1][mt], bf[0][nt]);
                    MMA16816(accL[mt][nt], af[1][mt], bf[1][nt]);
                    MMA16816(accL[mt][nt], af[0][mt], bf[2][nt]);
                    MMA16816(accL[mt][nt], af[2][mt], bf[0][nt]);
                }
        }
        __syncthreads();

        if (s & 1) {   // k128 drain period (bit-identical to prior rounds)
#pragma unroll
            for (int mt = 0; mt < 2; ++mt)
#pragma unroll
                for (int nt = 0; nt < 4; ++nt)
#pragma unroll
                    for (int q = 0; q < 4; ++q) {
                        accS[mt][nt][q] += accH[mt][nt][q];
                        accH[mt][nt][q] = 0.f;
                    }
        }
    }

    const int l4 = lane >> 2, l2 = (lane & 3) * 2;
#pragma unroll
    for (int mt = 0; mt < 2; ++mt)
#pragma unroll
        for (int rh = 0; rh < 2; ++rh) {
            const int row = m0 + warp_m * 32 + mt * 16 + rh * 8 + l4;
#pragma unroll
            for (int nt = 0; nt < 4; ++nt) {
                const int c = n0 + warp_n * 32 + nt * 8 + l2;
                const int a = c >> 10, e = c & 1023;
                double x0 = (double)accS[mt][nt][rh * 2 + 0] + (double)accL[mt][nt][rh * 2 + 0];
                double x1 = (double)accS[mt][nt][rh * 2 + 1] + (double)accL[mt][nt][rh * 2 + 1];
                const int tt = row >> 8, b = row & 255;
                size_t oidx = ((size_t)((tt * 3 + a) * 256 + b)) * 1024 + e;
                *(float2*)&dout[oidx] = make_float2((float)x0, (float)x1);
            }
        }
}

// ---------------- Phase 2: persistent step kernel with grid barrier ----------------
// 128 CTAs (tile 128x48), all resident (1 CTA/SM via smem, 128 <= 148 SMs).
// t-loop inside; software grid barrier between steps. Inner math identical
// to R14's step_gemm -> bit-identical results.
__global__ __launch_bounds__(256) void step_persist(float* __restrict__ dout) {
    constexpr int S = N_ / 64;   // 48 stages
    extern __shared__ char smem[];
    const uint32_t sb = smem_u32(smem);
    const int tid = threadIdx.x, wid = tid >> 5, lane = tid & 31;
    const int warp_m = wid & 3, warp_n = wid >> 2;
    const int n0 = blockIdx.x * 48;
    const int m0 = blockIdx.y * 128;

    const int r16 = lane & 15, ahi = (lane >> 4) * 16;
    uint32_t aoff[2];
#pragma unroll
    for (int mt = 0; mt < 2; ++mt)
        aoff[mt] = (uint32_t)(warp_m * 32 + mt * 16 + r16) * 144 + ahi;
    const int bg = lane >> 3, bri = lane & 7;
    const uint32_t boff4 = (uint32_t)(warp_n * 24 + ((bg >> 1) << 3) + bri) * 144 + (bg & 1) * 16;
    const uint32_t boff2 = (uint32_t)(warp_n * 24 + 16 + bri) * 144 + (bg & 1) * 16;
    const int l4 = lane >> 2, l2 = (lane & 3) * 2;

    const __nv_bfloat16* __restrict__ Bsrc = g_WrecS[0];
    const size_t Bstride = (size_t)N_ * N_;
    const size_t Astride = (size_t)B_ * N_;

    for (int t = 0; t < T_; ++t) {
        const int par = t & 1;
        const __nv_bfloat16* __restrict__ Asrc = g_VS[par][0];

        float accH[2][3][4], accL[2][3][4], accS[2][3][4];
#pragma unroll
        for (int i = 0; i < 2; ++i)
#pragma unroll
            for (int j = 0; j < 3; ++j)
#pragma unroll
                for (int q = 0; q < 4; ++q) {
                    accH[i][j][q] = 0.f; accL[i][j][q] = 0.f; accS[i][j][q] = 0.f;
                }

        auto loadChunk = [&](int s, uint32_t buf) {
            const int kb = s * 64;
            for (int u = tid; u < 4224; u += 256) {
                const __nv_bfloat16* gp;
                uint32_t sa;
                if (u < 3072) {
                    int sp = u >> 10, rem = u & 1023, row = rem >> 3, un = rem & 7;
                    gp = Asrc + sp * Astride + (size_t)(m0 + row) * N_ + kb + un * 8;
                    sa = buf + sp * AS64 + row * 144 + un * 16;
                } else {
                    int v = u - 3072;
                    int sp = v / 384, rem = v - sp * 384, row = rem >> 3, un = rem & 7;
                    gp = Bsrc + sp * Bstride + (size_t)(n0 + row) * N_ + kb + un * 8;
                    sa = buf + OFFB64 + sp * BS64_ST + row * 144 + un * 16;
                }
                CPASYNC16(sa, gp);
            }
            asm volatile("cp.async.commit_group;" ::: "memory");
        };

        loadChunk(0, sb);

        for (int s = 0; s < S; ++s) {
            if (s + 1 < S) {
                loadChunk(s + 1, sb + (uint32_t)((s + 1) & 1) * BUF_ST);
                asm volatile("cp.async.wait_group 1;" ::: "memory");
            } else {
                asm volatile("cp.async.wait_group 0;" ::: "memory");
            }
            __syncthreads();

            const uint32_t buf = sb + (uint32_t)(s & 1) * BUF_ST;
#pragma unroll
            for (int kk = 0; kk < 4; ++kk) {
                uint32_t af[3][2][4], bf[3][3][2];
#pragma unroll
                for (int sp = 0; sp < 3; ++sp) {
                    uint32_t ab = buf + sp * AS64 + kk * 32;
#pragma unroll
                    for (int mt = 0; mt < 2; ++mt)
                        LDSM4(af[sp][mt][0], af[sp][mt][1], af[sp][mt][2], af[sp][mt][3],
                              ab + aoff[mt]);
                    uint32_t bb = buf + OFFB64 + sp * BS64_ST + kk * 32;
                    LDSM4(bf[sp][0][0], bf[sp][0][1], bf[sp][1][0], bf[sp][1][1], bb + boff4);
                    LDSM2(bf[sp][2][0], bf[sp][2][1], bb + boff2);
                }
#pragma unroll
                for (int mt = 0; mt < 2; ++mt)
#pragma unroll
                    for (int nt = 0; nt < 3; ++nt) {
                        MMA16816(accH[mt][nt], af[0][mt], bf[0][nt]);
                        MMA16816(accL[mt][nt], af[0][mt], bf[1][nt]);
                        MMA16816(accL[mt][nt], af[1][mt], bf[0][nt]);
                        MMA16816(accL[mt][nt], af[1][mt], bf[1][nt]);
                        MMA16816(accL[mt][nt], af[0][mt], bf[2][nt]);
                        MMA16816(accL[mt][nt], af[2][mt], bf[0][nt]);
                    }
            }
            __syncthreads();

            if (s & 1) {   // k128 drain period
#pragma unroll
                for (int mt = 0; mt < 2; ++mt)
#pragma unroll
                    for (int nt = 0; nt < 3; ++nt)
#pragma unroll
                        for (int q = 0; q < 4; ++q) {
                            accS[mt][nt][q] += accH[mt][nt][q];
                            accH[mt][nt][q] = 0.f;
                        }
            }
        }

        // ---- epilogue: combine, clip, write h, produce next-step splits ----
#pragma unroll
        for (int mt = 0; mt < 2; ++mt)
#pragma unroll
            for (int rh = 0; rh < 2; ++rh) {
                const int b = m0 + warp_m * 32 + mt * 16 + rh * 8 + l4;
#pragma unroll
                for (int nt = 0; nt < 3; ++nt) {
                    const int c = n0 + warp_n * 24 + nt * 8 + l2;
                    const int a = c >> 10, e = c & 1023;
                    double x0 = (double)accS[mt][nt][rh * 2 + 0] + (double)accL[mt][nt][rh * 2 + 0];
                    double x1 = (double)accS[mt][nt][rh * 2 + 1] + (double)accL[mt][nt][rh * 2 + 1];
                    size_t oidx = ((size_t)((t * 3 + a) * 256 + b)) * 1024 + e;
                    float2 u = *(const float2*)&dout[oidx];
                    float2 v = *(const float2*)&g_V[par][(size_t)b * N_ + c];
                    float r0 = (float)fmin(1.0, fmax(-1.0, x0 + (double)u.x + (double)v.x));
                    float r1 = (float)fmin(1.0, fmax(-1.0, x1 + (double)u.y + (double)v.y));
                    *(float2*)&dout[oidx] = make_float2(r0, r1);
                    *(float2*)&g_V[par ^ 1][(size_t)b * N_ + c] = make_float2(r0, r1);
                    __nv_bfloat16 h0, mm0, l0, h1, mm1, l1;
                    split3(r0, h0, mm0, l0);
                    split3(r1, h1, mm1, l1);
                    size_t vidx = (size_t)b * N_ + c;
                    *(__nv_bfloat162*)&g_VS[par ^ 1][0][vidx] = __nv_bfloat162{h0, h1};
                    *(__nv_bfloat162*)&g_VS[par ^ 1][1][vidx] = __nv_bfloat162{mm0, mm1};
                    *(__nv_bfloat162*)&g_VS[par ^ 1][2][vidx] = __nv_bfloat162{l0, l1};
                }
            }

        // ---- grid barrier between steps ----
        if (t + 1 < T_) {
            __syncthreads();
            if (tid == 0) {
                __threadfence();                       // release our V/VS writes
                atomicAdd(&g_bar, 1u);
                const unsigned target = 128u * (unsigned)(t + 1);
                while (*(volatile unsigned*)&g_bar < target) { }
                __threadfence();                       // acquire peers' writes
            }
            __syncthreads();
        }
    }
}

// ------------------------------------------------------------------
extern "C" void kernel_launch(void* const* d_in, const int* in_sizes, int n_in,
                              void* d_out, int out_size) {
    (void)in_sizes; (void)n_in; (void)out_size;
    const float* ento = (const float*)d_in[0];   // [T,B,ENTO]
    const float* v0   = (const float*)d_in[1];   // [A,B,EM]
    const float* w_ih = (const float*)d_in[2];   // [A,EM,IN]
    const float* w_hh = (const float*)d_in[3];   // [A,EM,EM]
    float* out = (float*)d_out;                  // [T,A,B,EM]

    cudaFuncSetAttribute(phase1_gemm,  cudaFuncAttributeMaxDynamicSharedMemorySize, SMEM_P1);
    cudaFuncSetAttribute(step_persist, cudaFuncAttributeMaxDynamicSharedMemorySize, SMEM_ST);

    split_ento <<<dim3(ENTO_ / 256, MROWS), 256>>>(ento);
    split_wento<<<dim3(ENTO_ / 256, N_),    256>>>(w_ih);
    split_v0   <<<dim3(N_ / 256, B_),       256>>>(v0);

    // Phase 1 (4th launch — ncu capture slot): U = ento @ Wento^T into out
    phase1_gemm<<<dim3(32, 128), 384, SMEM_P1>>>(out);

    split_wrec <<<dim3(N_ / 256, N_),       256>>>(w_ih, w_hh);
    zero_bar   <<<1, 1>>>();

    // Phase 2: all 64 recurrent steps in ONE persistent kernel (128 CTAs)
    step_persist<<<dim3(64, 2), 256, SMEM_ST>>>(out);
}

// round 16
// speedup vs baseline: 2.0008x; 1.0493x over previous
#include <cuda_runtime.h>
#include <cuda_bf16.h>
#include <cstdint>
#include <cstddef>

#define A_    3
#define T_    64
#define B_    256
#define ENTO_ 2048
#define EM_   1024
#define IN_   4096
#define N_    3072
#define MROWS 16384

// ---------------- device scratch (static globals; no allocation) ----------------
__device__ __nv_bfloat16 g_EntoS [3][(size_t)MROWS * ENTO_];  // ento bf16 splits [row][k]
__device__ __nv_bfloat16 g_WentoS[3][(size_t)N_ * ENTO_];     // W_ento splits   [n][k]
__device__ __nv_bfloat16 g_WrecS [3][(size_t)N_ * N_];        // merged W splits [n][k]
__device__ __nv_bfloat16 g_VS[2][3][B_ * N_];                 // V splits, ping-pong [b][n]
__device__ float         g_V [2][B_ * N_];                    // V fp32, ping-pong  [b][n]
__device__ unsigned      g_bar;                               // grid barrier counter

// ---------------- helpers ----------------
__device__ __forceinline__ uint32_t smem_u32(const void* p) {
    uint32_t a;
    asm("{ .reg .u64 t; cvta.to.shared.u64 t, %1; cvt.u32.u64 %0, t; }" : "=r"(a) : "l"(p));
    return a;
}
__device__ __forceinline__ void split3(float f, __nv_bfloat16& h, __nv_bfloat16& m,
                                       __nv_bfloat16& l) {
    h = __float2bfloat16(f);
    float r = f - __bfloat162float(h);
    m = __float2bfloat16(r);
    r = r - __bfloat162float(m);
    l = __float2bfloat16(r);
}

#define LDSM4(r0, r1, r2, r3, addr) \
    asm volatile("ldmatrix.sync.aligned.m8n8.x4.shared.b16 {%0,%1,%2,%3}, [%4];" \
                 : "=r"(r0), "=r"(r1), "=r"(r2), "=r"(r3) : "r"(addr))

#define MMA16816(d, a, b) \
    asm volatile("mma.sync.aligned.m16n8k16.row.col.f32.bf16.bf16.f32 " \
                 "{%0,%1,%2,%3}, {%4,%5,%6,%7}, {%8,%9}, {%0,%1,%2,%3};" \
                 : "+f"((d)[0]), "+f"((d)[1]), "+f"((d)[2]), "+f"((d)[3]) \
                 : "r"((a)[0]), "r"((a)[1]), "r"((a)[2]), "r"((a)[3]), \
                   "r"((b)[0]), "r"((b)[1]))

#define CPASYNC16(dst, src) \
    asm volatile("cp.async.cg.shared.global [%0], [%1], 16;" :: "r"(dst), "l"(src))

// ---------------- prep (split) kernels ----------------
__global__ void split_ento(const float* __restrict__ ento) {
    int k = blockIdx.x * 256 + threadIdx.x;
    size_t idx = (size_t)blockIdx.y * ENTO_ + k;
    __nv_bfloat16 h, m, l; split3(ento[idx], h, m, l);
    g_EntoS[0][idx] = h; g_EntoS[1][idx] = m; g_EntoS[2][idx] = l;
}
__global__ void split_wento(const float* __restrict__ w_ih) {
    int k = blockIdx.x * 256 + threadIdx.x;
    int n = blockIdx.y;
    float f = w_ih[(size_t)n * IN_ + k];
    __nv_bfloat16 h, m, l; split3(f, h, m, l);
    size_t idx = (size_t)n * ENTO_ + k;
    g_WentoS[0][idx] = h; g_WentoS[1][idx] = m; g_WentoS[2][idx] = l;
}
__global__ void split_wrec(const float* __restrict__ w_ih, const float* __restrict__ w_hh) {
    int k = blockIdx.x * 256 + threadIdx.x;
    int n = blockIdx.y;
    int j = k >> 10, m_ = k & 1023;
    int a = n >> 10;
    float f;
    if (j == a) f = w_hh[(size_t)n * EM_ + m_];
    else {
        int pos = j - (j > a ? 1 : 0);
        f = w_ih[(size_t)n * IN_ + ENTO_ + pos * EM_ + m_];
    }
    __nv_bfloat16 h, m, l; split3(f, h, m, l);
    size_t idx = (size_t)n * N_ + k;
    g_WrecS[0][idx] = h; g_WrecS[1][idx] = m; g_WrecS[2][idx] = l;
}
__global__ void split_v0(const float* __restrict__ v0) {
    int n = blockIdx.x * 256 + threadIdx.x;
    int b = blockIdx.y;
    int j = n >> 10, m_ = n & 1023;
    float f = v0[((size_t)j * B_ + b) * EM_ + m_];
    g_V[0][b * N_ + n] = f;
    __nv_bfloat16 h, m, l; split3(f, h, m, l);
    g_VS[0][0][b * N_ + n] = h;
    g_VS[0][1][b * N_ + n] = m;
    g_VS[0][2][b * N_ + n] = l;
}
__global__ void zero_bar() { g_bar = 0; }

// ---------------- k64-staged bf16x3 HMMA kernels ----------------
#define AS64      18432          /* 128*144 A-split bytes */
#define OFFB64    55296          /* 3*AS64 */

// Phase 1: CTA 128x96, 384 threads (12 warps 4m x 3n), grid (32, 128)
#define BS64_P1   13824          /* 96*144 */
#define BUF_P1    96768          /* OFFB64 + 3*BS64_P1 */
#define SMEM_P1  193536

// Phase 2: CTA 128x48, 384 threads (12 warps 4m x 3n, warp tile 32x16),
// grid (64, 2) = 128 CTAs, persistent
#define BS64_ST    6912          /* 48*144 */
#define BUF_ST    76032          /* OFFB64 + 3*BS64_ST */
#define SMEM_ST  152064

__global__ __launch_bounds__(384) void phase1_gemm(float* __restrict__ dout) {
    constexpr int S = ENTO_ / 64;   // 32 stages
    extern __shared__ char smem[];
    const uint32_t sb = smem_u32(smem);
    const int tid = threadIdx.x, wid = tid >> 5, lane = tid & 31;
    const int warp_m = wid & 3, warp_n = wid >> 2;   // 4m x 3n
    const int n0 = blockIdx.x * 96;
    const int m0 = blockIdx.y * 128;

    float accH[2][4][4], accL[2][4][4], accS[2][4][4];
#pragma unroll
    for (int i = 0; i < 2; ++i)
#pragma unroll
        for (int j = 0; j < 4; ++j)
#pragma unroll
            for (int q = 0; q < 4; ++q) {
                accH[i][j][q] = 0.f; accL[i][j][q] = 0.f; accS[i][j][q] = 0.f;
            }

    auto loadChunk = [&](int s, uint32_t buf) {
        const int kb = s * 64;
#pragma unroll
        for (int i = 0; i < 14; ++i) {
            int u = tid + i * 384;
            const __nv_bfloat16* gp;
            uint32_t sa;
            if (u < 3072) {
                int sp = u >> 10, rem = u & 1023, row = rem >> 3, un = rem & 7;
                gp = g_EntoS[sp] + (size_t)(m0 + row) * ENTO_ + kb + un * 8;
                sa = buf + sp * AS64 + row * 144 + un * 16;
            } else {
                int v = u - 3072;
                int sp = v / 768, rem = v - sp * 768, row = rem >> 3, un = rem & 7;
                gp = g_WentoS[sp] + (size_t)(n0 + row) * ENTO_ + kb + un * 8;
                sa = buf + OFFB64 + sp * BS64_P1 + row * 144 + un * 16;
            }
            CPASYNC16(sa, gp);
        }
        asm volatile("cp.async.commit_group;" ::: "memory");
    };

    const int r16 = lane & 15, ahi = (lane >> 4) * 16;
    uint32_t aoff[2];
#pragma unroll
    for (int mt = 0; mt < 2; ++mt)
        aoff[mt] = (uint32_t)(warp_m * 32 + mt * 16 + r16) * 144 + ahi;
    const int bg = lane >> 3, bri = lane & 7;
    uint32_t boff[2];
#pragma unroll
    for (int p = 0; p < 2; ++p)
        boff[p] = (uint32_t)(warp_n * 32 + p * 16 + ((bg >> 1) << 3) + bri) * 144 + (bg & 1) * 16;

    loadChunk(0, sb);

    for (int s = 0; s < S; ++s) {
        if (s + 1 < S) {
            loadChunk(s + 1, sb + (uint32_t)((s + 1) & 1) * BUF_P1);
            asm volatile("cp.async.wait_group 1;" ::: "memory");
        } else {
            asm volatile("cp.async.wait_group 0;" ::: "memory");
        }
        __syncthreads();

        const uint32_t buf = sb + (uint32_t)(s & 1) * BUF_P1;
#pragma unroll
        for (int kk = 0; kk < 4; ++kk) {
            uint32_t af[3][2][4], bf[3][4][2];
#pragma unroll
            for (int sp = 0; sp < 3; ++sp) {
                uint32_t ab = buf + sp * AS64 + kk * 32;
#pragma unroll
                for (int mt = 0; mt < 2; ++mt)
                    LDSM4(af[sp][mt][0], af[sp][mt][1], af[sp][mt][2], af[sp][mt][3],
                          ab + aoff[mt]);
                uint32_t bb = buf + OFFB64 + sp * BS64_P1 + kk * 32;
#pragma unroll
                for (int p = 0; p < 2; ++p)
                    LDSM4(bf[sp][2 * p][0], bf[sp][2 * p][1],
                          bf[sp][2 * p + 1][0], bf[sp][2 * p + 1][1],
                          bb + boff[p]);
            }
#pragma unroll
            for (int mt = 0; mt < 2; ++mt)
#pragma unroll
                for (int nt = 0; nt < 4; ++nt) {
                    MMA16816(accH[mt][nt], af[0][mt], bf[0][nt]);
                    MMA16816(accL[mt][nt], af[0][mt], bf[1][nt]);
                    MMA16816(accL[mt][nt], af[1][mt], bf[0][nt]);
                    MMA16816(accL[mt][nt], af[1][mt], bf[1][nt]);
                    MMA16816(accL[mt][nt], af[0][mt], bf[2][nt]);
                    MMA16816(accL[mt][nt], af[2][mt], bf[0][nt]);
                }
        }
        __syncthreads();

        if (s & 1) {   // k128 drain period (bit-identical to prior rounds)
#pragma unroll
            for (int mt = 0; mt < 2; ++mt)
#pragma unroll
                for (int nt = 0; nt < 4; ++nt)
#pragma unroll
                    for (int q = 0; q < 4; ++q) {
                        accS[mt][nt][q] += accH[mt][nt][q];
                        accH[mt][nt][q] = 0.f;
                    }
        }
    }

    const int l4 = lane >> 2, l2 = (lane & 3) * 2;
#pragma unroll
    for (int mt = 0; mt < 2; ++mt)
#pragma unroll
        for (int rh = 0; rh < 2; ++rh) {
            const int row = m0 + warp_m * 32 + mt * 16 + rh * 8 + l4;
#pragma unroll
            for (int nt = 0; nt < 4; ++nt) {
                const int c = n0 + warp_n * 32 + nt * 8 + l2;
                const int a = c >> 10, e = c & 1023;
                double x0 = (double)accS[mt][nt][rh * 2 + 0] + (double)accL[mt][nt][rh * 2 + 0];
                double x1 = (double)accS[mt][nt][rh * 2 + 1] + (double)accL[mt][nt][rh * 2 + 1];
                const int tt = row >> 8, b = row & 255;
                size_t oidx = ((size_t)((tt * 3 + a) * 256 + b)) * 1024 + e;
                *(float2*)&dout[oidx] = make_float2((float)x0, (float)x1);
            }
        }
}

// ---------------- Phase 2: persistent step kernel, 384 threads ----------------
// 128 CTAs (tile 128x48), all resident. 12 warps as 4(m)x3(n): warp tile
// 32x16 = 2mt x 2nt m16n8 tiles -> 3 warps/SMSP (phase1-proven latency hiding).
// Same products / accumulator banks / k-order / drain -> bit-identical results.
__global__ __launch_bounds__(384) void step_persist(float* __restrict__ dout) {
    constexpr int S = N_ / 64;   // 48 stages
    extern __shared__ char smem[];
    const uint32_t sb = smem_u32(smem);
    const int tid = threadIdx.x, wid = tid >> 5, lane = tid & 31;
    const int warp_m = wid & 3, warp_n = wid >> 2;   // 4m x 3n
    const int n0 = blockIdx.x * 48;
    const int m0 = blockIdx.y * 128;

    const int r16 = lane & 15, ahi = (lane >> 4) * 16;
    uint32_t aoff[2];
#pragma unroll
    for (int mt = 0; mt < 2; ++mt)
        aoff[mt] = (uint32_t)(warp_m * 32 + mt * 16 + r16) * 144 + ahi;
    const int bg = lane >> 3, bri = lane & 7;
    // one LDSM4 covers the warp's 16 B-rows (2 n-tiles x 2 k-halves)
    const uint32_t boff = (uint32_t)(warp_n * 16 + ((bg >> 1) << 3) + bri) * 144 + (bg & 1) * 16;
    const int l4 = lane >> 2, l2 = (lane & 3) * 2;

    const __nv_bfloat16* __restrict__ Bsrc = g_WrecS[0];
    const size_t Bstride = (size_t)N_ * N_;
    const size_t Astride = (size_t)B_ * N_;

    for (int t = 0; t < T_; ++t) {
        const int par = t & 1;
        const __nv_bfloat16* __restrict__ Asrc = g_VS[par][0];

        float accH[2][2][4], accL[2][2][4], accS[2][2][4];
#pragma unroll
        for (int i = 0; i < 2; ++i)
#pragma unroll
            for (int j = 0; j < 2; ++j)
#pragma unroll
                for (int q = 0; q < 4; ++q) {
                    accH[i][j][q] = 0.f; accL[i][j][q] = 0.f; accS[i][j][q] = 0.f;
                }

        auto loadChunk = [&](int s, uint32_t buf) {
            const int kb = s * 64;
            for (int u = tid; u < 4224; u += 384) {
                const __nv_bfloat16* gp;
                uint32_t sa;
                if (u < 3072) {
                    int sp = u >> 10, rem = u & 1023, row = rem >> 3, un = rem & 7;
                    gp = Asrc + sp * Astride + (size_t)(m0 + row) * N_ + kb + un * 8;
                    sa = buf + sp * AS64 + row * 144 + un * 16;
                } else {
                    int v = u - 3072;
                    int sp = v / 384, rem = v - sp * 384, row = rem >> 3, un = rem & 7;
                    gp = Bsrc + sp * Bstride + (size_t)(n0 + row) * N_ + kb + un * 8;
                    sa = buf + OFFB64 + sp * BS64_ST + row * 144 + un * 16;
                }
                CPASYNC16(sa, gp);
            }
            asm volatile("cp.async.commit_group;" ::: "memory");
        };

        loadChunk(0, sb);

        for (int s = 0; s < S; ++s) {
            if (s + 1 < S) {
                loadChunk(s + 1, sb + (uint32_t)((s + 1) & 1) * BUF_ST);
                asm volatile("cp.async.wait_group 1;" ::: "memory");
            } else {
                asm volatile("cp.async.wait_group 0;" ::: "memory");
            }
            __syncthreads();

            const uint32_t buf = sb + (uint32_t)(s & 1) * BUF_ST;
#pragma unroll
            for (int kk = 0; kk < 4; ++kk) {
                uint32_t af[3][2][4], bf[3][2][2];
#pragma unroll
                for (int sp = 0; sp < 3; ++sp) {
                    uint32_t ab = buf + sp * AS64 + kk * 32;
#pragma unroll
                    for (int mt = 0; mt < 2; ++mt)
                        LDSM4(af[sp][mt][0], af[sp][mt][1], af[sp][mt][2], af[sp][mt][3],
                              ab + aoff[mt]);
                    uint32_t bb = buf + OFFB64 + sp * BS64_ST + kk * 32;
                    LDSM4(bf[sp][0][0], bf[sp][0][1], bf[sp][1][0], bf[sp][1][1], bb + boff);
                }
#pragma unroll
                for (int mt = 0; mt < 2; ++mt)
#pragma unroll
                    for (int nt = 0; nt < 2; ++nt) {
                        MMA16816(accH[mt][nt], af[0][mt], bf[0][nt]);
                        MMA16816(accL[mt][nt], af[0][mt], bf[1][nt]);
                        MMA16816(accL[mt][nt], af[1][mt], bf[0][nt]);
                        MMA16816(accL[mt][nt], af[1][mt], bf[1][nt]);
                        MMA16816(accL[mt][nt], af[0][mt], bf[2][nt]);
                        MMA16816(accL[mt][nt], af[2][mt], bf[0][nt]);
                    }
            }
            __syncthreads();

            if (s & 1) {   // k128 drain period
#pragma unroll
                for (int mt = 0; mt < 2; ++mt)
#pragma unroll
                    for (int nt = 0; nt < 2; ++nt)
#pragma unroll
                        for (int q = 0; q < 4; ++q) {
                            accS[mt][nt][q] += accH[mt][nt][q];
                            accH[mt][nt][q] = 0.f;
                        }
            }
        }

        // ---- epilogue: combine, clip, write h, produce next-step splits ----
#pragma unroll
        for (int mt = 0; mt < 2; ++mt)
#pragma unroll
            for (int rh = 0; rh < 2; ++rh) {
                const int b = m0 + warp_m * 32 + mt * 16 + rh * 8 + l4;
#pragma unroll
                for (int nt = 0; nt < 2; ++nt) {
                    const int c = n0 + warp_n * 16 + nt * 8 + l2;
                    const int a = c >> 10, e = c & 1023;
                    double x0 = (double)accS[mt][nt][rh * 2 + 0] + (double)accL[mt][nt][rh * 2 + 0];
                    double x1 = (double)accS[mt][nt][rh * 2 + 1] + (double)accL[mt][nt][rh * 2 + 1];
                    size_t oidx = ((size_t)((t * 3 + a) * 256 + b)) * 1024 + e;
                    float2 u = *(const float2*)&dout[oidx];
                    float2 v = *(const float2*)&g_V[par][(size_t)b * N_ + c];
                    float r0 = (float)fmin(1.0, fmax(-1.0, x0 + (double)u.x + (double)v.x));
                    float r1 = (float)fmin(1.0, fmax(-1.0, x1 + (double)u.y + (double)v.y));
                    *(float2*)&dout[oidx] = make_float2(r0, r1);
                    *(float2*)&g_V[par ^ 1][(size_t)b * N_ + c] = make_float2(r0, r1);
                    __nv_bfloat16 h0, mm0, l0, h1, mm1, l1;
                    split3(r0, h0, mm0, l0);
                    split3(r1, h1, mm1, l1);
                    size_t vidx = (size_t)b * N_ + c;
                    *(__nv_bfloat162*)&g_VS[par ^ 1][0][vidx] = __nv_bfloat162{h0, h1};
                    *(__nv_bfloat162*)&g_VS[par ^ 1][1][vidx] = __nv_bfloat162{mm0, mm1};
                    *(__nv_bfloat162*)&g_VS[par ^ 1][2][vidx] = __nv_bfloat162{l0, l1};
                }
            }

        // ---- grid barrier between steps ----
        if (t + 1 < T_) {
            __syncthreads();
            if (tid == 0) {
                __threadfence();                       // release our V/VS writes
                atomicAdd(&g_bar, 1u);
                const unsigned target = 128u * (unsigned)(t + 1);
                while (*(volatile unsigned*)&g_bar < target) { }
                __threadfence();                       // acquire peers' writes
            }
            __syncthreads();
        }
    }
}

// ------------------------------------------------------------------
extern "C" void kernel_launch(void* const* d_in, const int* in_sizes, int n_in,
                              void* d_out, int out_size) {
    (void)in_sizes; (void)n_in; (void)out_size;
    const float* ento = (const float*)d_in[0];   // [T,B,ENTO]
    const float* v0   = (const float*)d_in[1];   // [A,B,EM]
    const float* w_ih = (const float*)d_in[2];   // [A,EM,IN]
    const float* w_hh = (const float*)d_in[3];   // [A,EM,EM]
    float* out = (float*)d_out;                  // [T,A,B,EM]

    cudaFuncSetAttribute(phase1_gemm,  cudaFuncAttributeMaxDynamicSharedMemorySize, SMEM_P1);
    cudaFuncSetAttribute(step_persist, cudaFuncAttributeMaxDynamicSharedMemorySize, SMEM_ST);

    split_ento <<<dim3(ENTO_ / 256, MROWS), 256>>>(ento);
    split_wento<<<dim3(ENTO_ / 256, N_),    256>>>(w_ih);
    split_v0   <<<dim3(N_ / 256, B_),       256>>>(v0);

    // Phase 1 (4th launch — ncu capture slot): U = ento @ Wento^T into out
    phase1_gemm<<<dim3(32, 128), 384, SMEM_P1>>>(out);

    split_wrec <<<dim3(N_ / 256, N_),       256>>>(w_ih, w_hh);
    zero_bar   <<<1, 1>>>();

    // Phase 2: all 64 recurrent steps in ONE persistent kernel (128 CTAs, 384 thr)
    step_persist<<<dim3(64, 2), 384, SMEM_ST>>>(out);
}